// round 1
// baseline (speedup 1.0000x reference)
#include <cuda_runtime.h>

#define BATCH 2
#define SEQ   2048
#define DIM   2048
#define NH    16
#define HD    128
#define MROWS (BATCH*SEQ)   // 4096
#define DFF   8192

// ---- scratch (allocation-free rule: __device__ globals) ----
__device__ float g_q[(size_t)MROWS * DIM];
__device__ float g_k[(size_t)MROWS * DIM];
__device__ float g_v[(size_t)MROWS * DIM];
__device__ float g_attn[(size_t)MROWS * DIM];
__device__ float g_ln1[(size_t)MROWS * DIM];
__device__ float g_h[(size_t)MROWS * DFF];

// =====================================================================
// GEMM: C[M,N] = A[M,K] @ B[K,N]   (row-major everywhere)
// EPI 0: none
// EPI 1: +bias then exact GELU
// EPI 2: +bias +res
// Block tile 128x128, K-tile 16, 256 threads, 8x8 per-thread microtile.
// =====================================================================
template<int EPI>
__global__ void __launch_bounds__(256, 2) gemm_kernel(
    const float* __restrict__ A, const float* __restrict__ B,
    float* __restrict__ C, const float* __restrict__ bias,
    const float* __restrict__ res, int N, int K)
{
    __shared__ float As[16][128];   // transposed: As[k][m]
    __shared__ float Bs[16][128];   // Bs[k][n]

    const int tid  = threadIdx.x;
    const int warp = tid >> 5, lane = tid & 31;
    const int wr = lane >> 3, wc = lane & 7;         // 4x8 lanes in warp
    const int row0 = (warp >> 1) * 32 + wr * 8;       // warp tile 32x64
    const int col0 = (warp & 1) * 64 + wc * 8;
    const int m0 = blockIdx.y * 128, n0 = blockIdx.x * 128;

    const int a_r = tid >> 2,  a_c = (tid & 3) << 2;   // A loader
    const int b_r = tid >> 5,  b_c = (tid & 31) << 2;  // B loader

    float acc[8][8];
    #pragma unroll
    for (int i = 0; i < 8; i++)
        #pragma unroll
        for (int j = 0; j < 8; j++) acc[i][j] = 0.f;

    for (int kt = 0; kt < K; kt += 16) {
        #pragma unroll
        for (int p = 0; p < 2; p++) {
            float4 v = *(const float4*)&A[(size_t)(m0 + a_r + p*64) * K + kt + a_c];
            As[a_c + 0][a_r + p*64] = v.x;
            As[a_c + 1][a_r + p*64] = v.y;
            As[a_c + 2][a_r + p*64] = v.z;
            As[a_c + 3][a_r + p*64] = v.w;
        }
        #pragma unroll
        for (int p = 0; p < 2; p++) {
            *(float4*)&Bs[b_r + p*8][b_c] =
                *(const float4*)&B[(size_t)(kt + b_r + p*8) * N + n0 + b_c];
        }
        __syncthreads();
        #pragma unroll
        for (int kk = 0; kk < 16; kk++) {
            float a[8], b[8];
            *(float4*)&a[0] = *(const float4*)&As[kk][row0];
            *(float4*)&a[4] = *(const float4*)&As[kk][row0 + 4];
            *(float4*)&b[0] = *(const float4*)&Bs[kk][col0];
            *(float4*)&b[4] = *(const float4*)&Bs[kk][col0 + 4];
            #pragma unroll
            for (int i = 0; i < 8; i++)
                #pragma unroll
                for (int j = 0; j < 8; j++)
                    acc[i][j] += a[i] * b[j];
        }
        __syncthreads();
    }

    #pragma unroll
    for (int i = 0; i < 8; i++) {
        size_t gr = (size_t)(m0 + row0 + i);
        #pragma unroll
        for (int j4 = 0; j4 < 8; j4 += 4) {
            int gc = n0 + col0 + j4;
            float t[4];
            #pragma unroll
            for (int u = 0; u < 4; u++) {
                float x = acc[i][j4 + u];
                if (EPI == 1) {
                    x += bias[gc + u];
                    x = 0.5f * x * (1.0f + erff(x * 0.70710678118654752f));
                } else if (EPI == 2) {
                    x += bias[gc + u] + res[gr * N + gc + u];
                }
                t[u] = x;
            }
            float4 v; v.x = t[0]; v.y = t[1]; v.z = t[2]; v.w = t[3];
            *(float4*)&C[gr * N + gc] = v;
        }
    }
}

// =====================================================================
// RoPE — NOTE: reference indexes sin/cos by BATCH index (L = x.shape[0] = B),
// not by sequence position. Every row in batch b uses sin[b,:], cos[b,:].
// out[j]      = x[2j]*c[j] - x[2j+1]*s[j]          j in [0,1024)
// out[1024+j] = x[2j]*s[j] + x[2j+1]*c[j]
// =====================================================================
__global__ void __launch_bounds__(256) rope_kernel(
    float* __restrict__ x, const float* __restrict__ sinp,
    const float* __restrict__ cosp)
{
    __shared__ float row[DIM];
    const int r = blockIdx.x;
    const int b = r / SEQ;
    const size_t base = (size_t)r * DIM;
    for (int i = threadIdx.x; i < DIM/4; i += 256)
        *(float4*)&row[i * 4] = *(const float4*)&x[base + i * 4];
    __syncthreads();
    for (int j = threadIdx.x; j < DIM/2; j += 256) {
        float x1 = row[2*j], x2 = row[2*j + 1];
        float c = cosp[b * (DIM/2) + j];
        float s = sinp[b * (DIM/2) + j];
        x[base + j]           = x1 * c - x2 * s;
        x[base + (DIM/2) + j] = x1 * s + x2 * c;
    }
}

// =====================================================================
// Flash attention, fp32. Per block: one (b, h, 64-query tile).
// 256 threads as 16x16: thread (ti,tj) owns S rows ti*4..+3 / cols tj*4..+3
// and O rows ti*4..+3 / cols tj*8..+7. K/V/Q smem pitch 132 to break the
// 16-way bank conflict of column-of-rows float4 reads (now 2-way).
// =====================================================================
#define APITCH 132

__global__ void __launch_bounds__(256, 1) attn_kernel()
{
    extern __shared__ float sm[];
    float* Qs = sm;                        // 64 * 132
    float* Ks = Qs + 64 * APITCH;          // 64 * 132
    float* Vs = Ks + 64 * APITCH;          // 64 * 132
    float* Ps = Vs + 64 * APITCH;          // 64 * 64

    const int qb = blockIdx.x, h = blockIdx.y, b = blockIdx.z;
    const int tid = threadIdx.x;
    const int ti = tid >> 4, tj = tid & 15;
    const float scale = 0.08838834764831845f;  // 1/sqrt(128)

    const size_t qbase = ((size_t)(b * SEQ + qb * 64)) * DIM + h * HD;
    for (int idx = tid; idx < 64 * 32; idx += 256) {
        int r = idx >> 5, c4 = (idx & 31) << 2;
        float4 v = *(const float4*)&g_q[qbase + (size_t)r * DIM + c4];
        v.x *= scale; v.y *= scale; v.z *= scale; v.w *= scale;
        *(float4*)&Qs[r * APITCH + c4] = v;
    }

    float o[4][8], m_[4], l_[4];
    #pragma unroll
    for (int r = 0; r < 4; r++) {
        m_[r] = -1e30f; l_[r] = 0.f;
        #pragma unroll
        for (int c = 0; c < 8; c++) o[r][c] = 0.f;
    }

    for (int kt = 0; kt <= qb; kt++) {
        __syncthreads();   // prior O-accum done before K/V/P reuse
        const size_t kbase = ((size_t)(b * SEQ + kt * 64)) * DIM + h * HD;
        for (int idx = tid; idx < 64 * 32; idx += 256) {
            int r = idx >> 5, c4 = (idx & 31) << 2;
            *(float4*)&Ks[r * APITCH + c4] = *(const float4*)&g_k[kbase + (size_t)r * DIM + c4];
            *(float4*)&Vs[r * APITCH + c4] = *(const float4*)&g_v[kbase + (size_t)r * DIM + c4];
        }
        __syncthreads();

        // S = Q K^T (scaled; scale folded into Qs)
        float s[4][4];
        #pragma unroll
        for (int r = 0; r < 4; r++)
            #pragma unroll
            for (int c = 0; c < 4; c++) s[r][c] = 0.f;

        for (int d = 0; d < HD; d += 4) {
            float4 qv[4], kv[4];
            #pragma unroll
            for (int r = 0; r < 4; r++)
                qv[r] = *(const float4*)&Qs[(ti*4 + r) * APITCH + d];
            #pragma unroll
            for (int c = 0; c < 4; c++)
                kv[c] = *(const float4*)&Ks[(tj*4 + c) * APITCH + d];
            #pragma unroll
            for (int r = 0; r < 4; r++)
                #pragma unroll
                for (int c = 0; c < 4; c++)
                    s[r][c] += qv[r].x*kv[c].x + qv[r].y*kv[c].y
                             + qv[r].z*kv[c].z + qv[r].w*kv[c].w;
        }

        if (kt == qb) {  // causal mask on diagonal tile
            #pragma unroll
            for (int r = 0; r < 4; r++)
                #pragma unroll
                for (int c = 0; c < 4; c++)
                    if (tj*4 + c > ti*4 + r) s[r][c] = -1e30f;
        }

        // online softmax (16 lanes per row-group share stats via shfl)
        #pragma unroll
        for (int r = 0; r < 4; r++) {
            float mx = fmaxf(fmaxf(s[r][0], s[r][1]), fmaxf(s[r][2], s[r][3]));
            #pragma unroll
            for (int d = 8; d >= 1; d >>= 1)
                mx = fmaxf(mx, __shfl_xor_sync(0xffffffffu, mx, d));
            float mn    = fmaxf(m_[r], mx);
            float alpha = __expf(m_[r] - mn);
            float p0 = __expf(s[r][0] - mn), p1 = __expf(s[r][1] - mn);
            float p2 = __expf(s[r][2] - mn), p3 = __expf(s[r][3] - mn);
            float rs = p0 + p1 + p2 + p3;
            #pragma unroll
            for (int d = 8; d >= 1; d >>= 1)
                rs += __shfl_xor_sync(0xffffffffu, rs, d);
            m_[r] = mn;
            l_[r] = l_[r] * alpha + rs;
            #pragma unroll
            for (int c = 0; c < 8; c++) o[r][c] *= alpha;
            Ps[(ti*4 + r) * 64 + tj*4 + 0] = p0;
            Ps[(ti*4 + r) * 64 + tj*4 + 1] = p1;
            Ps[(ti*4 + r) * 64 + tj*4 + 2] = p2;
            Ps[(ti*4 + r) * 64 + tj*4 + 3] = p3;
        }
        __syncthreads();

        // O += P @ V
        #pragma unroll 2
        for (int kk = 0; kk < 64; kk++) {
            float4 v0 = *(const float4*)&Vs[kk * APITCH + tj*8];
            float4 v1 = *(const float4*)&Vs[kk * APITCH + tj*8 + 4];
            #pragma unroll
            for (int r = 0; r < 4; r++) {
                float p = Ps[(ti*4 + r) * 64 + kk];
                o[r][0] += p * v0.x; o[r][1] += p * v0.y;
                o[r][2] += p * v0.z; o[r][3] += p * v0.w;
                o[r][4] += p * v1.x; o[r][5] += p * v1.y;
                o[r][6] += p * v1.z; o[r][7] += p * v1.w;
            }
        }
    }

    #pragma unroll
    for (int r = 0; r < 4; r++) {
        float inv = 1.0f / l_[r];
        size_t row = (size_t)(b * SEQ + qb * 64 + ti*4 + r);
        float4 v0, v1;
        v0.x = o[r][0]*inv; v0.y = o[r][1]*inv; v0.z = o[r][2]*inv; v0.w = o[r][3]*inv;
        v1.x = o[r][4]*inv; v1.y = o[r][5]*inv; v1.z = o[r][6]*inv; v1.w = o[r][7]*inv;
        *(float4*)&g_attn[row * DIM + h*HD + tj*8]     = v0;
        *(float4*)&g_attn[row * DIM + h*HD + tj*8 + 4] = v1;
    }
}

// =====================================================================
// LayerNorm over last dim (2048). One block per row. Biased variance.
// ADDX: also add residual stream `add` before normalizing.
// =====================================================================
template<bool ADDX>
__global__ void __launch_bounds__(256) ln_kernel(
    const float* __restrict__ in, const float* __restrict__ add,
    float* __restrict__ out)
{
    __shared__ float redS[8], redQ[8];
    const int tid = threadIdx.x;
    const size_t base = (size_t)blockIdx.x * DIM;
    float v[8];
    float s = 0.f, q = 0.f;
    #pragma unroll
    for (int k = 0; k < 8; k++) {
        float a = in[base + tid + k*256];
        if (ADDX) a += add[base + tid + k*256];
        v[k] = a; s += a; q += a * a;
    }
    #pragma unroll
    for (int d = 16; d >= 1; d >>= 1) {
        s += __shfl_xor_sync(0xffffffffu, s, d);
        q += __shfl_xor_sync(0xffffffffu, q, d);
    }
    if ((tid & 31) == 0) { redS[tid >> 5] = s; redQ[tid >> 5] = q; }
    __syncthreads();
    float ts = 0.f, tq = 0.f;
    #pragma unroll
    for (int w = 0; w < 8; w++) { ts += redS[w]; tq += redQ[w]; }
    float mean = ts * (1.f / DIM);
    float var  = tq * (1.f / DIM) - mean * mean;
    float rstd = rsqrtf(var + 1e-5f);
    #pragma unroll
    for (int k = 0; k < 8; k++)
        out[base + tid + k*256] = (v[k] - mean) * rstd;
}

// =====================================================================
extern "C" void kernel_launch(void* const* d_in, const int* in_sizes, int n_in,
                              void* d_out, int out_size)
{
    const float* x    = (const float*)d_in[0];
    const float* Wq   = (const float*)d_in[1];
    const float* Wk   = (const float*)d_in[2];
    const float* Wv   = (const float*)d_in[3];
    const float* W1   = (const float*)d_in[4];
    const float* b1   = (const float*)d_in[5];
    const float* W2   = (const float*)d_in[6];
    const float* b2   = (const float*)d_in[7];
    const float* sinp = (const float*)d_in[8];
    const float* cosp = (const float*)d_in[9];
    float* out = (float*)d_out;

    float *q, *k, *v, *attn, *ln1, *hbuf;
    cudaGetSymbolAddress((void**)&q,    g_q);
    cudaGetSymbolAddress((void**)&k,    g_k);
    cudaGetSymbolAddress((void**)&v,    g_v);
    cudaGetSymbolAddress((void**)&attn, g_attn);
    cudaGetSymbolAddress((void**)&ln1,  g_ln1);
    cudaGetSymbolAddress((void**)&hbuf, g_h);

    const dim3 thr(256);

    // QKV projections
    gemm_kernel<0><<<dim3(DIM/128, MROWS/128), thr>>>(x, Wq, q, nullptr, nullptr, DIM, DIM);
    gemm_kernel<0><<<dim3(DIM/128, MROWS/128), thr>>>(x, Wk, k, nullptr, nullptr, DIM, DIM);
    gemm_kernel<0><<<dim3(DIM/128, MROWS/128), thr>>>(x, Wv, v, nullptr, nullptr, DIM, DIM);

    // RoPE (batch-indexed sin/cos — reference quirk)
    rope_kernel<<<MROWS, thr>>>(q, sinp, cosp);
    rope_kernel<<<MROWS, thr>>>(k, sinp, cosp);

    // Causal flash attention
    size_t smem = (size_t)(3 * 64 * APITCH + 64 * 64) * sizeof(float);
    cudaFuncSetAttribute(attn_kernel, cudaFuncAttributeMaxDynamicSharedMemorySize, (int)smem);
    attn_kernel<<<dim3(SEQ/64, NH, BATCH), thr, smem>>>();

    // LN1 with residual
    ln_kernel<true><<<MROWS, thr>>>(attn, x, ln1);

    // MLP
    gemm_kernel<1><<<dim3(DFF/128, MROWS/128), thr>>>(ln1, W1, hbuf, b1, nullptr, DFF, DIM);
    gemm_kernel<2><<<dim3(DIM/128, MROWS/128), thr>>>(hbuf, W2, q, b2, ln1, DIM, DFF);

    // LN2 -> output
    ln_kernel<false><<<MROWS, thr>>>(q, nullptr, out);
}

// round 3
// speedup vs baseline: 2.0229x; 2.0229x over previous
#include <cuda_runtime.h>
#include <cstdint>

#define BATCH 2
#define SEQ   2048
#define DIM   2048
#define NH    16
#define HD    128
#define MROWS (BATCH*SEQ)   // 4096
#define DFF   8192

// ---- scratch (allocation-free rule: __device__ globals) ----
__device__ float g_q[(size_t)MROWS * DIM];
__device__ float g_k[(size_t)MROWS * DIM];
__device__ float g_v[(size_t)MROWS * DIM];
__device__ float g_attn[(size_t)MROWS * DIM];
__device__ float g_ln1[(size_t)MROWS * DIM];
__device__ float g_h[(size_t)MROWS * DFF];

// =====================================================================
// tf32 helpers
// =====================================================================
__device__ __forceinline__ float tf32r(float x) {
    float r;
    asm("cvt.rna.tf32.f32 %0, %1;" : "=f"(r) : "f"(x));
    return r;
}

__device__ __forceinline__ void mma_tf32(float (&d)[4],
                                         const uint32_t (&a)[4],
                                         const uint32_t (&b)[2]) {
    asm volatile(
        "mma.sync.aligned.m16n8k8.row.col.f32.tf32.tf32.f32 "
        "{%0,%1,%2,%3}, {%4,%5,%6,%7}, {%8,%9}, {%0,%1,%2,%3};"
        : "+f"(d[0]), "+f"(d[1]), "+f"(d[2]), "+f"(d[3])
        : "r"(a[0]), "r"(a[1]), "r"(a[2]), "r"(a[3]),
          "r"(b[0]), "r"(b[1]));
}

// =====================================================================
// tf32 tensor-core GEMM: C[M,N] = A[M,K] @ B[K,N]  (row-major)
// EPI 0: none | 1: +bias, exact GELU | 2: +bias +res
// Block 128x128, K-tile 32, 8 warps (2x4), warp tile 64x32, mma m16n8k8.
// As[128][36]: fragment read bank = (4r + c) -> conflict-free.
// Bs[32][136]: fragment read bank = (8c + r) -> conflict-free.
// =====================================================================
template<int EPI>
__global__ void __launch_bounds__(256, 2) gemm_tf32(
    const float* __restrict__ A, const float* __restrict__ B,
    float* __restrict__ C, const float* __restrict__ bias,
    const float* __restrict__ res, int N, int K)
{
    __shared__ float As[128][36];
    __shared__ float Bs[32][136];

    const int tid  = threadIdx.x;
    const int warp = tid >> 5, lane = tid & 31;
    const int wm = warp >> 2;          // 0..1
    const int wn = warp & 3;           // 0..3
    const int r  = lane >> 2;          // group id 0..7
    const int c  = lane & 3;           // thread-in-group 0..3
    const int m0 = blockIdx.y * 128, n0 = blockIdx.x * 128;

    // staging maps
    const int ar = tid >> 1, ac = (tid & 1) * 16;  // A: row, col-chunk
    const int br = tid >> 3, bc = (tid & 7) * 4;   // B: row, col base

    float acc[4][4][4];
    #pragma unroll
    for (int mt = 0; mt < 4; mt++)
        #pragma unroll
        for (int nt = 0; nt < 4; nt++)
            #pragma unroll
            for (int i = 0; i < 4; i++) acc[mt][nt][i] = 0.f;

    for (int kt = 0; kt < K; kt += 32) {
        // ---- stage A (128x32), convert to tf32 bits ----
        const float* gA = A + (size_t)(m0 + ar) * K + kt + ac;
        #pragma unroll
        for (int i = 0; i < 4; i++) {
            float4 v = *(const float4*)(gA + i * 4);
            float4 w;
            w.x = tf32r(v.x); w.y = tf32r(v.y);
            w.z = tf32r(v.z); w.w = tf32r(v.w);
            *(float4*)&As[ar][ac + i * 4] = w;
        }
        // ---- stage B (32x128) ----
        const float* gB = B + (size_t)(kt + br) * N + n0 + bc;
        #pragma unroll
        for (int i = 0; i < 4; i++) {
            float4 v = *(const float4*)(gB + i * 32);
            float4 w;
            w.x = tf32r(v.x); w.y = tf32r(v.y);
            w.z = tf32r(v.z); w.w = tf32r(v.w);
            *(float4*)&Bs[br][bc + i * 32] = w;
        }
        __syncthreads();

        #pragma unroll
        for (int ks = 0; ks < 32; ks += 8) {
            uint32_t af[4][4];
            uint32_t bf[4][2];
            #pragma unroll
            for (int mt = 0; mt < 4; mt++) {
                int am = wm * 64 + mt * 16;
                af[mt][0] = __float_as_uint(As[am + r    ][ks + c    ]);
                af[mt][1] = __float_as_uint(As[am + r + 8][ks + c    ]);
                af[mt][2] = __float_as_uint(As[am + r    ][ks + c + 4]);
                af[mt][3] = __float_as_uint(As[am + r + 8][ks + c + 4]);
            }
            #pragma unroll
            for (int nt = 0; nt < 4; nt++) {
                int bn = wn * 32 + nt * 8;
                bf[nt][0] = __float_as_uint(Bs[ks + c    ][bn + r]);
                bf[nt][1] = __float_as_uint(Bs[ks + c + 4][bn + r]);
            }
            #pragma unroll
            for (int mt = 0; mt < 4; mt++)
                #pragma unroll
                for (int nt = 0; nt < 4; nt++)
                    mma_tf32(acc[mt][nt], af[mt], bf[nt]);
        }
        __syncthreads();
    }

    // ---- epilogue ----
    #pragma unroll
    for (int mt = 0; mt < 4; mt++) {
        #pragma unroll
        for (int nt = 0; nt < 4; nt++) {
            int col = n0 + wn * 32 + nt * 8 + 2 * c;
            #pragma unroll
            for (int half = 0; half < 2; half++) {
                size_t row = (size_t)(m0 + wm * 64 + mt * 16 + r + half * 8);
                float x0 = acc[mt][nt][half * 2 + 0];
                float x1 = acc[mt][nt][half * 2 + 1];
                if (EPI == 1) {
                    x0 += bias[col];
                    x1 += bias[col + 1];
                    x0 = 0.5f * x0 * (1.0f + erff(x0 * 0.70710678118654752f));
                    x1 = 0.5f * x1 * (1.0f + erff(x1 * 0.70710678118654752f));
                } else if (EPI == 2) {
                    x0 += bias[col]     + res[row * N + col];
                    x1 += bias[col + 1] + res[row * N + col + 1];
                }
                float2 v; v.x = x0; v.y = x1;
                *(float2*)&C[row * N + col] = v;
            }
        }
    }
}

// =====================================================================
// RoPE — reference indexes sin/cos by BATCH index (L = x.shape[0] = B).
// =====================================================================
__global__ void __launch_bounds__(256) rope_kernel(
    float* __restrict__ x, const float* __restrict__ sinp,
    const float* __restrict__ cosp)
{
    __shared__ float row[DIM];
    const int r = blockIdx.x;
    const int b = r / SEQ;
    const size_t base = (size_t)r * DIM;
    for (int i = threadIdx.x; i < DIM/4; i += 256)
        *(float4*)&row[i * 4] = *(const float4*)&x[base + i * 4];
    __syncthreads();
    for (int j = threadIdx.x; j < DIM/2; j += 256) {
        float x1 = row[2*j], x2 = row[2*j + 1];
        float c = cosp[b * (DIM/2) + j];
        float s = sinp[b * (DIM/2) + j];
        x[base + j]           = x1 * c - x2 * s;
        x[base + (DIM/2) + j] = x1 * s + x2 * c;
    }
}

// =====================================================================
// Flash attention, fp32 scalar (unchanged from R1)
// =====================================================================
#define APITCH 132

__global__ void __launch_bounds__(256, 1) attn_kernel()
{
    extern __shared__ float sm[];
    float* Qs = sm;                        // 64 * 132
    float* Ks = Qs + 64 * APITCH;          // 64 * 132
    float* Vs = Ks + 64 * APITCH;          // 64 * 132
    float* Ps = Vs + 64 * APITCH;          // 64 * 64

    const int qb = blockIdx.x, h = blockIdx.y, b = blockIdx.z;
    const int tid = threadIdx.x;
    const int ti = tid >> 4, tj = tid & 15;
    const float scale = 0.08838834764831845f;  // 1/sqrt(128)

    const size_t qbase = ((size_t)(b * SEQ + qb * 64)) * DIM + h * HD;
    for (int idx = tid; idx < 64 * 32; idx += 256) {
        int r = idx >> 5, c4 = (idx & 31) << 2;
        float4 v = *(const float4*)&g_q[qbase + (size_t)r * DIM + c4];
        v.x *= scale; v.y *= scale; v.z *= scale; v.w *= scale;
        *(float4*)&Qs[r * APITCH + c4] = v;
    }

    float o[4][8], m_[4], l_[4];
    #pragma unroll
    for (int r = 0; r < 4; r++) {
        m_[r] = -1e30f; l_[r] = 0.f;
        #pragma unroll
        for (int c = 0; c < 8; c++) o[r][c] = 0.f;
    }

    for (int kt = 0; kt <= qb; kt++) {
        __syncthreads();
        const size_t kbase = ((size_t)(b * SEQ + kt * 64)) * DIM + h * HD;
        for (int idx = tid; idx < 64 * 32; idx += 256) {
            int r = idx >> 5, c4 = (idx & 31) << 2;
            *(float4*)&Ks[r * APITCH + c4] = *(const float4*)&g_k[kbase + (size_t)r * DIM + c4];
            *(float4*)&Vs[r * APITCH + c4] = *(const float4*)&g_v[kbase + (size_t)r * DIM + c4];
        }
        __syncthreads();

        float s[4][4];
        #pragma unroll
        for (int r = 0; r < 4; r++)
            #pragma unroll
            for (int c = 0; c < 4; c++) s[r][c] = 0.f;

        for (int d = 0; d < HD; d += 4) {
            float4 qv[4], kv[4];
            #pragma unroll
            for (int r = 0; r < 4; r++)
                qv[r] = *(const float4*)&Qs[(ti*4 + r) * APITCH + d];
            #pragma unroll
            for (int c = 0; c < 4; c++)
                kv[c] = *(const float4*)&Ks[(tj*4 + c) * APITCH + d];
            #pragma unroll
            for (int r = 0; r < 4; r++)
                #pragma unroll
                for (int c = 0; c < 4; c++)
                    s[r][c] += qv[r].x*kv[c].x + qv[r].y*kv[c].y
                             + qv[r].z*kv[c].z + qv[r].w*kv[c].w;
        }

        if (kt == qb) {
            #pragma unroll
            for (int r = 0; r < 4; r++)
                #pragma unroll
                for (int c = 0; c < 4; c++)
                    if (tj*4 + c > ti*4 + r) s[r][c] = -1e30f;
        }

        #pragma unroll
        for (int r = 0; r < 4; r++) {
            float mx = fmaxf(fmaxf(s[r][0], s[r][1]), fmaxf(s[r][2], s[r][3]));
            #pragma unroll
            for (int d = 8; d >= 1; d >>= 1)
                mx = fmaxf(mx, __shfl_xor_sync(0xffffffffu, mx, d));
            float mn    = fmaxf(m_[r], mx);
            float alpha = __expf(m_[r] - mn);
            float p0 = __expf(s[r][0] - mn), p1 = __expf(s[r][1] - mn);
            float p2 = __expf(s[r][2] - mn), p3 = __expf(s[r][3] - mn);
            float rs = p0 + p1 + p2 + p3;
            #pragma unroll
            for (int d = 8; d >= 1; d >>= 1)
                rs += __shfl_xor_sync(0xffffffffu, rs, d);
            m_[r] = mn;
            l_[r] = l_[r] * alpha + rs;
            #pragma unroll
            for (int c = 0; c < 8; c++) o[r][c] *= alpha;
            Ps[(ti*4 + r) * 64 + tj*4 + 0] = p0;
            Ps[(ti*4 + r) * 64 + tj*4 + 1] = p1;
            Ps[(ti*4 + r) * 64 + tj*4 + 2] = p2;
            Ps[(ti*4 + r) * 64 + tj*4 + 3] = p3;
        }
        __syncthreads();

        #pragma unroll 2
        for (int kk = 0; kk < 64; kk++) {
            float4 v0 = *(const float4*)&Vs[kk * APITCH + tj*8];
            float4 v1 = *(const float4*)&Vs[kk * APITCH + tj*8 + 4];
            #pragma unroll
            for (int r = 0; r < 4; r++) {
                float p = Ps[(ti*4 + r) * 64 + kk];
                o[r][0] += p * v0.x; o[r][1] += p * v0.y;
                o[r][2] += p * v0.z; o[r][3] += p * v0.w;
                o[r][4] += p * v1.x; o[r][5] += p * v1.y;
                o[r][6] += p * v1.z; o[r][7] += p * v1.w;
            }
        }
    }

    #pragma unroll
    for (int r = 0; r < 4; r++) {
        float inv = 1.0f / l_[r];
        size_t row = (size_t)(b * SEQ + qb * 64 + ti*4 + r);
        float4 v0, v1;
        v0.x = o[r][0]*inv; v0.y = o[r][1]*inv; v0.z = o[r][2]*inv; v0.w = o[r][3]*inv;
        v1.x = o[r][4]*inv; v1.y = o[r][5]*inv; v1.z = o[r][6]*inv; v1.w = o[r][7]*inv;
        *(float4*)&g_attn[row * DIM + h*HD + tj*8]     = v0;
        *(float4*)&g_attn[row * DIM + h*HD + tj*8 + 4] = v1;
    }
}

// =====================================================================
// LayerNorm over last dim (2048). One block per row. Biased variance.
// =====================================================================
template<bool ADDX>
__global__ void __launch_bounds__(256) ln_kernel(
    const float* __restrict__ in, const float* __restrict__ add,
    float* __restrict__ out)
{
    __shared__ float redS[8], redQ[8];
    const int tid = threadIdx.x;
    const size_t base = (size_t)blockIdx.x * DIM;
    float v[8];
    float s = 0.f, q = 0.f;
    #pragma unroll
    for (int k = 0; k < 8; k++) {
        float a = in[base + tid + k*256];
        if (ADDX) a += add[base + tid + k*256];
        v[k] = a; s += a; q += a * a;
    }
    #pragma unroll
    for (int d = 16; d >= 1; d >>= 1) {
        s += __shfl_xor_sync(0xffffffffu, s, d);
        q += __shfl_xor_sync(0xffffffffu, q, d);
    }
    if ((tid & 31) == 0) { redS[tid >> 5] = s; redQ[tid >> 5] = q; }
    __syncthreads();
    float ts = 0.f, tq = 0.f;
    #pragma unroll
    for (int w = 0; w < 8; w++) { ts += redS[w]; tq += redQ[w]; }
    float mean = ts * (1.f / DIM);
    float var  = tq * (1.f / DIM) - mean * mean;
    float rstd = rsqrtf(var + 1e-5f);
    #pragma unroll
    for (int k = 0; k < 8; k++)
        out[base + tid + k*256] = (v[k] - mean) * rstd;
}

// =====================================================================
extern "C" void kernel_launch(void* const* d_in, const int* in_sizes, int n_in,
                              void* d_out, int out_size)
{
    const float* x    = (const float*)d_in[0];
    const float* Wq   = (const float*)d_in[1];
    const float* Wk   = (const float*)d_in[2];
    const float* Wv   = (const float*)d_in[3];
    const float* W1   = (const float*)d_in[4];
    const float* b1   = (const float*)d_in[5];
    const float* W2   = (const float*)d_in[6];
    const float* b2   = (const float*)d_in[7];
    const float* sinp = (const float*)d_in[8];
    const float* cosp = (const float*)d_in[9];
    float* out = (float*)d_out;

    float *q, *k, *v, *attn, *ln1, *hbuf;
    cudaGetSymbolAddress((void**)&q,    g_q);
    cudaGetSymbolAddress((void**)&k,    g_k);
    cudaGetSymbolAddress((void**)&v,    g_v);
    cudaGetSymbolAddress((void**)&attn, g_attn);
    cudaGetSymbolAddress((void**)&ln1,  g_ln1);
    cudaGetSymbolAddress((void**)&hbuf, g_h);

    const dim3 thr(256);

    // QKV projections (tf32 tensor cores)
    gemm_tf32<0><<<dim3(DIM/128, MROWS/128), thr>>>(x, Wq, q, nullptr, nullptr, DIM, DIM);
    gemm_tf32<0><<<dim3(DIM/128, MROWS/128), thr>>>(x, Wk, k, nullptr, nullptr, DIM, DIM);
    gemm_tf32<0><<<dim3(DIM/128, MROWS/128), thr>>>(x, Wv, v, nullptr, nullptr, DIM, DIM);

    // RoPE (batch-indexed sin/cos — reference quirk)
    rope_kernel<<<MROWS, thr>>>(q, sinp, cosp);
    rope_kernel<<<MROWS, thr>>>(k, sinp, cosp);

    // Causal flash attention
    size_t smem = (size_t)(3 * 64 * APITCH + 64 * 64) * sizeof(float);
    cudaFuncSetAttribute(attn_kernel, cudaFuncAttributeMaxDynamicSharedMemorySize, (int)smem);
    attn_kernel<<<dim3(SEQ/64, NH, BATCH), thr, smem>>>();

    // LN1 with residual
    ln_kernel<true><<<MROWS, thr>>>(attn, x, ln1);

    // MLP (tf32 tensor cores)
    gemm_tf32<1><<<dim3(DFF/128, MROWS/128), thr>>>(ln1, W1, hbuf, b1, nullptr, DFF, DIM);
    gemm_tf32<2><<<dim3(DIM/128, MROWS/128), thr>>>(hbuf, W2, q, b2, ln1, DIM, DFF);

    // LN2 -> output
    ln_kernel<false><<<MROWS, thr>>>(q, nullptr, out);
}

// round 6
// speedup vs baseline: 3.7913x; 1.8742x over previous
#include <cuda_runtime.h>
#include <cstdint>

#define BATCH 2
#define SEQ   2048
#define DIM   2048
#define NH    16
#define HD    128
#define MROWS (BATCH*SEQ)   // 4096
#define DFF   8192

// ---- scratch (allocation-free rule: __device__ globals) ----
__device__ float g_q[(size_t)MROWS * DIM];
__device__ float g_k[(size_t)MROWS * DIM];
__device__ float g_v[(size_t)MROWS * DIM];
__device__ float g_attn[(size_t)MROWS * DIM];
__device__ float g_ln1[(size_t)MROWS * DIM];
__device__ float g_h[(size_t)MROWS * DFF];
// tf32-clean operand copies
__device__ float g_xt [(size_t)MROWS * DIM];
__device__ float g_wqt[(size_t)DIM * DIM];
__device__ float g_wkt[(size_t)DIM * DIM];
__device__ float g_wvt[(size_t)DIM * DIM];
__device__ float g_w1t[(size_t)DIM * DFF];
__device__ float g_w2t[(size_t)DFF * DIM];
__device__ float g_ln1t[(size_t)MROWS * DIM];

// =====================================================================
// helpers
// =====================================================================
__device__ __forceinline__ float tf32r(float x) {
    float r;
    asm("cvt.rna.tf32.f32 %0, %1;" : "=f"(r) : "f"(x));
    return r;
}

__device__ __forceinline__ void mma_tf32(float (&d)[4],
                                         const uint32_t (&a)[4],
                                         const uint32_t (&b)[2]) {
    asm volatile(
        "mma.sync.aligned.m16n8k8.row.col.f32.tf32.tf32.f32 "
        "{%0,%1,%2,%3}, {%4,%5,%6,%7}, {%8,%9}, {%0,%1,%2,%3};"
        : "+f"(d[0]), "+f"(d[1]), "+f"(d[2]), "+f"(d[3])
        : "r"(a[0]), "r"(a[1]), "r"(a[2]), "r"(a[3]),
          "r"(b[0]), "r"(b[1]));
}

__device__ __forceinline__ void cp16(void* sdst, const void* gsrc) {
    uint32_t s = (uint32_t)__cvta_generic_to_shared(sdst);
    asm volatile("cp.async.cg.shared.global [%0], [%1], 16;\n" :: "r"(s), "l"(gsrc));
}

// elementwise tf32 rounding copy (float4 grid-stride)
__global__ void __launch_bounds__(256) cvt_tf32_kernel(
    const float* __restrict__ in, float* __restrict__ out, size_t n4)
{
    size_t stride = (size_t)gridDim.x * blockDim.x;
    for (size_t i = (size_t)blockIdx.x * blockDim.x + threadIdx.x; i < n4; i += stride) {
        float4 v = ((const float4*)in)[i];
        v.x = tf32r(v.x); v.y = tf32r(v.y);
        v.z = tf32r(v.z); v.w = tf32r(v.w);
        ((float4*)out)[i] = v;
    }
}

// =====================================================================
// tf32 tensor-core GEMM, 3-stage cp.async pipeline, 1 sync / k-tile.
// C[M,N] = A[M,K] @ B[K,N]; A,B must be tf32-clean fp32.
// EPI 0: none | 1: +bias, exact GELU, tf32-rounded output | 2: +bias +res
// Block 128x128, K-tile 32, 8 warps (2x4), warp tile 64x32.
// =====================================================================
#define GSTAGES 3
#define GSMEM_BYTES ((GSTAGES*128*36 + GSTAGES*32*136) * 4)

template<int EPI>
__global__ void __launch_bounds__(256, 2) gemm_tc(
    const float* __restrict__ A, const float* __restrict__ B,
    float* __restrict__ C, const float* __restrict__ bias,
    const float* __restrict__ res, int N, int K)
{
    extern __shared__ float sh[];
    float (*As)[128][36] = (float(*)[128][36])sh;
    float (*Bs)[32][136] = (float(*)[32][136])(sh + GSTAGES*128*36);

    const int tid  = threadIdx.x;
    const int warp = tid >> 5, lane = tid & 31;
    const int wm = warp >> 2;          // 0..1
    const int wn = warp & 3;           // 0..3
    const int r  = lane >> 2;          // 0..7
    const int c  = lane & 3;           // 0..3
    const int m0 = blockIdx.y * 128, n0 = blockIdx.x * 128;

    const int arow = tid >> 3;          // 0..31
    const int acol = (tid & 7) * 4;     // 0..28
    const int brow = tid >> 5;          // 0..7
    const int bcol = (tid & 31) * 4;    // 0..124

    const int T = K >> 5;

    auto issue_tile = [&](int t, int buf) {
        #pragma unroll
        for (int i = 0; i < 4; i++)
            cp16(&As[buf][arow + i*32][acol],
                 A + (size_t)(m0 + arow + i*32) * K + t*32 + acol);
        #pragma unroll
        for (int i = 0; i < 4; i++)
            cp16(&Bs[buf][brow + i*8][bcol],
                 B + (size_t)(t*32 + brow + i*8) * N + n0 + bcol);
        asm volatile("cp.async.commit_group;\n");
    };

    float acc[4][4][4];
    #pragma unroll
    for (int mt = 0; mt < 4; mt++)
        #pragma unroll
        for (int nt = 0; nt < 4; nt++)
            #pragma unroll
            for (int i = 0; i < 4; i++) acc[mt][nt][i] = 0.f;

    issue_tile(0, 0);
    issue_tile(1, 1);

    int buf = 0;
    for (int t = 0; t < T; t++) {
        asm volatile("cp.async.wait_group 1;\n");
        __syncthreads();
        if (t + 2 < T) {
            int nb = buf + 2; if (nb >= GSTAGES) nb -= GSTAGES;   // correct wrap
            issue_tile(t + 2, nb);
        } else {
            asm volatile("cp.async.commit_group;\n");
        }

        #pragma unroll
        for (int ks = 0; ks < 32; ks += 8) {
            uint32_t af[4][4];
            uint32_t bf[4][2];
            #pragma unroll
            for (int mt = 0; mt < 4; mt++) {
                int am = wm * 64 + mt * 16;
                af[mt][0] = __float_as_uint(As[buf][am + r    ][ks + c    ]);
                af[mt][1] = __float_as_uint(As[buf][am + r + 8][ks + c    ]);
                af[mt][2] = __float_as_uint(As[buf][am + r    ][ks + c + 4]);
                af[mt][3] = __float_as_uint(As[buf][am + r + 8][ks + c + 4]);
            }
            #pragma unroll
            for (int nt = 0; nt < 4; nt++) {
                int bn = wn * 32 + nt * 8;
                bf[nt][0] = __float_as_uint(Bs[buf][ks + c    ][bn + r]);
                bf[nt][1] = __float_as_uint(Bs[buf][ks + c + 4][bn + r]);
            }
            #pragma unroll
            for (int mt = 0; mt < 4; mt++)
                #pragma unroll
                for (int nt = 0; nt < 4; nt++)
                    mma_tf32(acc[mt][nt], af[mt], bf[nt]);
        }
        buf++; if (buf == GSTAGES) buf = 0;
    }

    // ---- epilogue ----
    #pragma unroll
    for (int mt = 0; mt < 4; mt++) {
        #pragma unroll
        for (int nt = 0; nt < 4; nt++) {
            int col = n0 + wn * 32 + nt * 8 + 2 * c;
            #pragma unroll
            for (int half = 0; half < 2; half++) {
                size_t row = (size_t)(m0 + wm * 64 + mt * 16 + r + half * 8);
                float x0 = acc[mt][nt][half * 2 + 0];
                float x1 = acc[mt][nt][half * 2 + 1];
                if (EPI == 1) {
                    x0 += bias[col];
                    x1 += bias[col + 1];
                    x0 = tf32r(0.5f * x0 * (1.0f + erff(x0 * 0.70710678118654752f)));
                    x1 = tf32r(0.5f * x1 * (1.0f + erff(x1 * 0.70710678118654752f)));
                } else if (EPI == 2) {
                    x0 += bias[col]     + res[row * N + col];
                    x1 += bias[col + 1] + res[row * N + col + 1];
                }
                float2 v; v.x = x0; v.y = x1;
                *(float2*)&C[row * N + col] = v;
            }
        }
    }
}

// =====================================================================
// RoPE — reference indexes sin/cos by BATCH index (L = x.shape[0] = B).
// =====================================================================
__global__ void __launch_bounds__(256) rope_kernel(
    float* __restrict__ x, const float* __restrict__ sinp,
    const float* __restrict__ cosp)
{
    __shared__ float row[DIM];
    const int r = blockIdx.x;
    const int b = r / SEQ;
    const size_t base = (size_t)r * DIM;
    for (int i = threadIdx.x; i < DIM/4; i += 256)
        *(float4*)&row[i * 4] = *(const float4*)&x[base + i * 4];
    __syncthreads();
    for (int j = threadIdx.x; j < DIM/2; j += 256) {
        float x1 = row[2*j], x2 = row[2*j + 1];
        float c = cosp[b * (DIM/2) + j];
        float s = sinp[b * (DIM/2) + j];
        x[base + j]           = x1 * c - x2 * s;
        x[base + (DIM/2) + j] = x1 * s + x2 * c;
    }
}

// =====================================================================
// Tensor-core flash attention (tf32 mma), BM=128 q-rows, BN=64 kv.
// 8 warps; warp w owns q rows w*16..w*16+15 -> softmax fully warp-local.
// =====================================================================
#define QP 132
#define KP 132
#define VP 136
#define PP 68
#define ATT_SMEM ((128*QP + 64*KP + 64*VP + 128*PP) * 4)

__global__ void __launch_bounds__(256, 1) attn_mma_kernel()
{
    extern __shared__ float sm[];
    float* Qs = sm;                  // 128 x QP
    float* Ks = Qs + 128 * QP;       // 64 x KP
    float* Vs = Ks + 64  * KP;       // 64 x VP
    float* Ps = Vs + 64  * VP;       // 128 x PP

    const int qb = (gridDim.x - 1) - blockIdx.x;  // heavy blocks first
    const int h = blockIdx.y, b = blockIdx.z;
    const int tid = threadIdx.x;
    const int w = tid >> 5, lane = tid & 31;
    const int grp = lane >> 2, c = lane & 3;
    const float scale = 0.08838834764831845f;  // 1/sqrt(128)

    // stage Q (128 x 128), scaled then tf32-rounded
    const size_t qbase = ((size_t)(b * SEQ + qb * 128)) * DIM + h * HD;
    for (int idx = tid; idx < 128 * 32; idx += 256) {
        int r = idx >> 5, c4 = (idx & 31) << 2;
        float4 v = *(const float4*)&g_q[qbase + (size_t)r * DIM + c4];
        v.x = tf32r(v.x * scale); v.y = tf32r(v.y * scale);
        v.z = tf32r(v.z * scale); v.w = tf32r(v.w * scale);
        *(float4*)&Qs[r * QP + c4] = v;
    }

    float o[16][4];
    #pragma unroll
    for (int nt = 0; nt < 16; nt++)
        #pragma unroll
        for (int i = 0; i < 4; i++) o[nt][i] = 0.f;
    float m0v = -1e30f, m1v = -1e30f, l0 = 0.f, l1 = 0.f;

    const int rowg0 = qb * 128 + w * 16 + grp;
    const int rowg1 = rowg0 + 8;
    const int ktiles = 2 * qb + 2;

    for (int kt = 0; kt < ktiles; kt++) {
        __syncthreads();  // protect K/V/P reuse (and Q staging on iter 0)
        const size_t kbase = ((size_t)(b * SEQ + kt * 64)) * DIM + h * HD;
        for (int idx = tid; idx < 64 * 32; idx += 256) {
            int r = idx >> 5, c4 = (idx & 31) << 2;
            float4 kv = *(const float4*)&g_k[kbase + (size_t)r * DIM + c4];
            kv.x = tf32r(kv.x); kv.y = tf32r(kv.y);
            kv.z = tf32r(kv.z); kv.w = tf32r(kv.w);
            *(float4*)&Ks[r * KP + c4] = kv;
            float4 vv = *(const float4*)&g_v[kbase + (size_t)r * DIM + c4];
            vv.x = tf32r(vv.x); vv.y = tf32r(vv.y);
            vv.z = tf32r(vv.z); vv.w = tf32r(vv.w);
            *(float4*)&Vs[r * VP + c4] = vv;
        }
        __syncthreads();

        // ---- S = Q K^T ----
        float sacc[8][4];
        #pragma unroll
        for (int nt = 0; nt < 8; nt++)
            #pragma unroll
            for (int i = 0; i < 4; i++) sacc[nt][i] = 0.f;

        #pragma unroll
        for (int d = 0; d < HD; d += 8) {
            uint32_t af[4];
            af[0] = __float_as_uint(Qs[(w*16 + grp    ) * QP + d + c    ]);
            af[1] = __float_as_uint(Qs[(w*16 + grp + 8) * QP + d + c    ]);
            af[2] = __float_as_uint(Qs[(w*16 + grp    ) * QP + d + c + 4]);
            af[3] = __float_as_uint(Qs[(w*16 + grp + 8) * QP + d + c + 4]);
            #pragma unroll
            for (int nt = 0; nt < 8; nt++) {
                uint32_t bf[2];
                bf[0] = __float_as_uint(Ks[(nt*8 + grp) * KP + d + c    ]);
                bf[1] = __float_as_uint(Ks[(nt*8 + grp) * KP + d + c + 4]);
                mma_tf32(sacc[nt], af, bf);
            }
        }

        // causal mask (only possible on the last two tiles)
        if (kt >= 2 * qb) {
            #pragma unroll
            for (int nt = 0; nt < 8; nt++) {
                int colg = kt * 64 + nt * 8 + 2 * c;
                if (colg     > rowg0) sacc[nt][0] = -1e30f;
                if (colg + 1 > rowg0) sacc[nt][1] = -1e30f;
                if (colg     > rowg1) sacc[nt][2] = -1e30f;
                if (colg + 1 > rowg1) sacc[nt][3] = -1e30f;
            }
        }

        // ---- online softmax (rows grp and grp+8, warp-local) ----
        float mx0 = -1e30f, mx1 = -1e30f;
        #pragma unroll
        for (int nt = 0; nt < 8; nt++) {
            mx0 = fmaxf(mx0, fmaxf(sacc[nt][0], sacc[nt][1]));
            mx1 = fmaxf(mx1, fmaxf(sacc[nt][2], sacc[nt][3]));
        }
        mx0 = fmaxf(mx0, __shfl_xor_sync(0xffffffffu, mx0, 1));
        mx0 = fmaxf(mx0, __shfl_xor_sync(0xffffffffu, mx0, 2));
        mx1 = fmaxf(mx1, __shfl_xor_sync(0xffffffffu, mx1, 1));
        mx1 = fmaxf(mx1, __shfl_xor_sync(0xffffffffu, mx1, 2));
        float mn0 = fmaxf(m0v, mx0), mn1 = fmaxf(m1v, mx1);
        float a0 = __expf(m0v - mn0), a1 = __expf(m1v - mn1);

        float s0 = 0.f, s1 = 0.f;
        #pragma unroll
        for (int nt = 0; nt < 8; nt++) {
            float p00 = tf32r(__expf(sacc[nt][0] - mn0));
            float p01 = tf32r(__expf(sacc[nt][1] - mn0));
            float p10 = tf32r(__expf(sacc[nt][2] - mn1));
            float p11 = tf32r(__expf(sacc[nt][3] - mn1));
            s0 += p00 + p01; s1 += p10 + p11;
            float2 e0; e0.x = p00; e0.y = p01;
            float2 e1; e1.x = p10; e1.y = p11;
            *(float2*)&Ps[(w*16 + grp    ) * PP + nt*8 + 2*c] = e0;
            *(float2*)&Ps[(w*16 + grp + 8) * PP + nt*8 + 2*c] = e1;
        }
        s0 += __shfl_xor_sync(0xffffffffu, s0, 1);
        s0 += __shfl_xor_sync(0xffffffffu, s0, 2);
        s1 += __shfl_xor_sync(0xffffffffu, s1, 1);
        s1 += __shfl_xor_sync(0xffffffffu, s1, 2);
        l0 = l0 * a0 + s0;
        l1 = l1 * a1 + s1;
        m0v = mn0; m1v = mn1;
        #pragma unroll
        for (int nt = 0; nt < 16; nt++) {
            o[nt][0] *= a0; o[nt][1] *= a0;
            o[nt][2] *= a1; o[nt][3] *= a1;
        }
        __syncwarp();

        // ---- O += P @ V ----
        #pragma unroll
        for (int kk = 0; kk < 8; kk++) {
            uint32_t af2[4];
            af2[0] = __float_as_uint(Ps[(w*16 + grp    ) * PP + kk*8 + c    ]);
            af2[1] = __float_as_uint(Ps[(w*16 + grp + 8) * PP + kk*8 + c    ]);
            af2[2] = __float_as_uint(Ps[(w*16 + grp    ) * PP + kk*8 + c + 4]);
            af2[3] = __float_as_uint(Ps[(w*16 + grp + 8) * PP + kk*8 + c + 4]);
            #pragma unroll
            for (int nt = 0; nt < 16; nt++) {
                uint32_t bf2[2];
                bf2[0] = __float_as_uint(Vs[(kk*8 + c    ) * VP + nt*8 + grp]);
                bf2[1] = __float_as_uint(Vs[(kk*8 + c + 4) * VP + nt*8 + grp]);
                mma_tf32(o[nt], af2, bf2);
            }
        }
    }

    // ---- writeout ----
    float inv0 = 1.0f / l0, inv1 = 1.0f / l1;
    size_t grow0 = (size_t)(b * SEQ + qb * 128 + w * 16 + grp);
    size_t grow1 = grow0 + 8;
    #pragma unroll
    for (int nt = 0; nt < 16; nt++) {
        int col = h * HD + nt * 8 + 2 * c;
        float2 v0; v0.x = o[nt][0] * inv0; v0.y = o[nt][1] * inv0;
        float2 v1; v1.x = o[nt][2] * inv1; v1.y = o[nt][3] * inv1;
        *(float2*)&g_attn[grow0 * DIM + col] = v0;
        *(float2*)&g_attn[grow1 * DIM + col] = v1;
    }
}

// =====================================================================
// LayerNorm over last dim (2048). Biased variance. Optional residual add
// and optional second tf32-rounded output (for GEMM A-operand).
// =====================================================================
template<bool ADDX, bool T32OUT>
__global__ void __launch_bounds__(256) ln_kernel(
    const float* __restrict__ in, const float* __restrict__ add,
    float* __restrict__ out, float* __restrict__ out_t)
{
    __shared__ float redS[8], redQ[8];
    const int tid = threadIdx.x;
    const size_t base = (size_t)blockIdx.x * DIM;
    float v[8];
    float s = 0.f, q = 0.f;
    #pragma unroll
    for (int k = 0; k < 8; k++) {
        float a = in[base + tid + k*256];
        if (ADDX) a += add[base + tid + k*256];
        v[k] = a; s += a; q += a * a;
    }
    #pragma unroll
    for (int d = 16; d >= 1; d >>= 1) {
        s += __shfl_xor_sync(0xffffffffu, s, d);
        q += __shfl_xor_sync(0xffffffffu, q, d);
    }
    if ((tid & 31) == 0) { redS[tid >> 5] = s; redQ[tid >> 5] = q; }
    __syncthreads();
    float ts = 0.f, tq = 0.f;
    #pragma unroll
    for (int wv = 0; wv < 8; wv++) { ts += redS[wv]; tq += redQ[wv]; }
    float mean = ts * (1.f / DIM);
    float var  = tq * (1.f / DIM) - mean * mean;
    float rstd = rsqrtf(var + 1e-5f);
    #pragma unroll
    for (int k = 0; k < 8; k++) {
        float y = (v[k] - mean) * rstd;
        out[base + tid + k*256] = y;
        if (T32OUT) out_t[base + tid + k*256] = tf32r(y);
    }
}

// =====================================================================
extern "C" void kernel_launch(void* const* d_in, const int* in_sizes, int n_in,
                              void* d_out, int out_size)
{
    const float* x    = (const float*)d_in[0];
    const float* Wq   = (const float*)d_in[1];
    const float* Wk   = (const float*)d_in[2];
    const float* Wv   = (const float*)d_in[3];
    const float* W1   = (const float*)d_in[4];
    const float* b1   = (const float*)d_in[5];
    const float* W2   = (const float*)d_in[6];
    const float* b2   = (const float*)d_in[7];
    const float* sinp = (const float*)d_in[8];
    const float* cosp = (const float*)d_in[9];
    float* out = (float*)d_out;

    float *q, *k, *v, *attn, *ln1, *hbuf;
    float *xt, *wqt, *wkt, *wvt, *w1t, *w2t, *ln1t;
    cudaGetSymbolAddress((void**)&q,    g_q);
    cudaGetSymbolAddress((void**)&k,    g_k);
    cudaGetSymbolAddress((void**)&v,    g_v);
    cudaGetSymbolAddress((void**)&attn, g_attn);
    cudaGetSymbolAddress((void**)&ln1,  g_ln1);
    cudaGetSymbolAddress((void**)&hbuf, g_h);
    cudaGetSymbolAddress((void**)&xt,   g_xt);
    cudaGetSymbolAddress((void**)&wqt,  g_wqt);
    cudaGetSymbolAddress((void**)&wkt,  g_wkt);
    cudaGetSymbolAddress((void**)&wvt,  g_wvt);
    cudaGetSymbolAddress((void**)&w1t,  g_w1t);
    cudaGetSymbolAddress((void**)&w2t,  g_w2t);
    cudaGetSymbolAddress((void**)&ln1t, g_ln1t);

    cudaFuncSetAttribute(gemm_tc<0>, cudaFuncAttributeMaxDynamicSharedMemorySize, GSMEM_BYTES);
    cudaFuncSetAttribute(gemm_tc<1>, cudaFuncAttributeMaxDynamicSharedMemorySize, GSMEM_BYTES);
    cudaFuncSetAttribute(gemm_tc<2>, cudaFuncAttributeMaxDynamicSharedMemorySize, GSMEM_BYTES);
    cudaFuncSetAttribute(attn_mma_kernel, cudaFuncAttributeMaxDynamicSharedMemorySize, ATT_SMEM);

    const dim3 thr(256);

    // tf32-clean operand prep
    cvt_tf32_kernel<<<2048, thr>>>(x,  xt,  ((size_t)MROWS*DIM)/4);
    cvt_tf32_kernel<<<2048, thr>>>(Wq, wqt, ((size_t)DIM*DIM)/4);
    cvt_tf32_kernel<<<2048, thr>>>(Wk, wkt, ((size_t)DIM*DIM)/4);
    cvt_tf32_kernel<<<2048, thr>>>(Wv, wvt, ((size_t)DIM*DIM)/4);
    cvt_tf32_kernel<<<2048, thr>>>(W1, w1t, ((size_t)DIM*DFF)/4);
    cvt_tf32_kernel<<<2048, thr>>>(W2, w2t, ((size_t)DFF*DIM)/4);

    // QKV projections
    gemm_tc<0><<<dim3(DIM/128, MROWS/128), thr, GSMEM_BYTES>>>(xt, wqt, q, nullptr, nullptr, DIM, DIM);
    gemm_tc<0><<<dim3(DIM/128, MROWS/128), thr, GSMEM_BYTES>>>(xt, wkt, k, nullptr, nullptr, DIM, DIM);
    gemm_tc<0><<<dim3(DIM/128, MROWS/128), thr, GSMEM_BYTES>>>(xt, wvt, v, nullptr, nullptr, DIM, DIM);

    // RoPE (batch-indexed sin/cos — reference quirk)
    rope_kernel<<<MROWS, thr>>>(q, sinp, cosp);
    rope_kernel<<<MROWS, thr>>>(k, sinp, cosp);

    // Tensor-core causal flash attention
    attn_mma_kernel<<<dim3(SEQ/128, NH, BATCH), thr, ATT_SMEM>>>();

    // LN1 with residual (fp32 out for residual; tf32 copy for MLP1 A)
    ln_kernel<true, true><<<MROWS, thr>>>(attn, x, ln1, ln1t);

    // MLP
    gemm_tc<1><<<dim3(DFF/128, MROWS/128), thr, GSMEM_BYTES>>>(ln1t, w1t, hbuf, b1, nullptr, DFF, DIM);
    gemm_tc<2><<<dim3(DIM/128, MROWS/128), thr, GSMEM_BYTES>>>(hbuf, w2t, q, b2, ln1, DIM, DFF);

    // LN2 -> output
    ln_kernel<false, false><<<MROWS, thr>>>(q, nullptr, out, nullptr);
}

// round 7
// speedup vs baseline: 4.0110x; 1.0579x over previous
#include <cuda_runtime.h>
#include <cstdint>

#define BATCH 2
#define SEQ   2048
#define DIM   2048
#define NH    16
#define HD    128
#define MROWS (BATCH*SEQ)   // 4096
#define DFF   8192

// ---- scratch (allocation-free rule: __device__ globals) ----
__device__ float g_q[(size_t)MROWS * DIM];
__device__ float g_k[(size_t)MROWS * DIM];
__device__ float g_v[(size_t)MROWS * DIM];
__device__ float g_attn[(size_t)MROWS * DIM];
__device__ float g_ln1[(size_t)MROWS * DIM];
__device__ float g_h[(size_t)MROWS * DFF];
// tf32-clean operand copies
__device__ float g_xt [(size_t)MROWS * DIM];
__device__ float g_wqt[(size_t)DIM * DIM];
__device__ float g_wkt[(size_t)DIM * DIM];
__device__ float g_wvt[(size_t)DIM * DIM];
__device__ float g_w1t[(size_t)DIM * DFF];
__device__ float g_w2t[(size_t)DFF * DIM];
__device__ float g_ln1t[(size_t)MROWS * DIM];

// =====================================================================
// helpers
// =====================================================================
__device__ __forceinline__ float tf32r(float x) {
    float r;
    asm("cvt.rna.tf32.f32 %0, %1;" : "=f"(r) : "f"(x));
    return r;
}

__device__ __forceinline__ void mma_tf32(float (&d)[4],
                                         const uint32_t (&a)[4],
                                         const uint32_t (&b)[2]) {
    asm volatile(
        "mma.sync.aligned.m16n8k8.row.col.f32.tf32.tf32.f32 "
        "{%0,%1,%2,%3}, {%4,%5,%6,%7}, {%8,%9}, {%0,%1,%2,%3};"
        : "+f"(d[0]), "+f"(d[1]), "+f"(d[2]), "+f"(d[3])
        : "r"(a[0]), "r"(a[1]), "r"(a[2]), "r"(a[3]),
          "r"(b[0]), "r"(b[1]));
}

__device__ __forceinline__ void cp16(void* sdst, const void* gsrc) {
    uint32_t s = (uint32_t)__cvta_generic_to_shared(sdst);
    asm volatile("cp.async.cg.shared.global [%0], [%1], 16;\n" :: "r"(s), "l"(gsrc));
}

// elementwise tf32 rounding copy (float4 grid-stride)
__global__ void __launch_bounds__(256) cvt_tf32_kernel(
    const float* __restrict__ in, float* __restrict__ out, size_t n4)
{
    size_t stride = (size_t)gridDim.x * blockDim.x;
    for (size_t i = (size_t)blockIdx.x * blockDim.x + threadIdx.x; i < n4; i += stride) {
        float4 v = ((const float4*)in)[i];
        v.x = tf32r(v.x); v.y = tf32r(v.y);
        v.z = tf32r(v.z); v.w = tf32r(v.w);
        ((float4*)out)[i] = v;
    }
}

// =====================================================================
// tf32 tensor-core GEMM, 3-stage cp.async pipeline, 1 barrier / k-tile.
// 128 threads (4 warps, 2x2), block tile 128x128, warp tile 64x64.
// 1.0 LDS per mma (vs 1.5 in the 8-warp 64x32 version).
// EPI 0: none | 1: +bias, exact GELU, round | 2: +bias +res | 3: round
// =====================================================================
#define GSTAGES 3
#define GSMEM_BYTES ((GSTAGES*128*36 + GSTAGES*32*136) * 4)

template<int EPI>
__global__ void __launch_bounds__(128, 2) gemm_tc(
    const float* __restrict__ A, const float* __restrict__ B,
    float* __restrict__ C, const float* __restrict__ bias,
    const float* __restrict__ res, int N, int K)
{
    extern __shared__ float sh[];
    float (*As)[128][36] = (float(*)[128][36])sh;
    float (*Bs)[32][136] = (float(*)[32][136])(sh + GSTAGES*128*36);

    const int tid  = threadIdx.x;
    const int warp = tid >> 5, lane = tid & 31;
    const int wm = warp >> 1;          // 0..1
    const int wn = warp & 1;           // 0..1
    const int r  = lane >> 2;          // 0..7
    const int c  = lane & 3;           // 0..3
    const int m0 = blockIdx.y * 128, n0 = blockIdx.x * 128;

    const int arow = tid >> 3,  acol = (tid & 7) * 4;   // A: 16 rows/step, 8 f4 per row
    const int brow = tid >> 5,  bcol = (tid & 31) * 4;  // B: 4 rows/step

    const int T = K >> 5;

    auto issue_tile = [&](int t, int buf) {
        #pragma unroll
        for (int i = 0; i < 8; i++)
            cp16(&As[buf][arow + i*16][acol],
                 A + (size_t)(m0 + arow + i*16) * K + t*32 + acol);
        #pragma unroll
        for (int i = 0; i < 8; i++)
            cp16(&Bs[buf][brow + i*4][bcol],
                 B + (size_t)(t*32 + brow + i*4) * N + n0 + bcol);
        asm volatile("cp.async.commit_group;\n");
    };

    float acc[4][8][4];
    #pragma unroll
    for (int mt = 0; mt < 4; mt++)
        #pragma unroll
        for (int nt = 0; nt < 8; nt++)
            #pragma unroll
            for (int i = 0; i < 4; i++) acc[mt][nt][i] = 0.f;

    issue_tile(0, 0);
    issue_tile(1, 1);

    int buf = 0;
    for (int t = 0; t < T; t++) {
        asm volatile("cp.async.wait_group 1;\n");
        __syncthreads();
        if (t + 2 < T) {
            int nb = buf + 2; if (nb >= GSTAGES) nb -= GSTAGES;
            issue_tile(t + 2, nb);
        } else {
            asm volatile("cp.async.commit_group;\n");
        }

        #pragma unroll
        for (int ks = 0; ks < 32; ks += 8) {
            uint32_t af[4][4];
            uint32_t bf[8][2];
            #pragma unroll
            for (int mt = 0; mt < 4; mt++) {
                int am = wm * 64 + mt * 16;
                af[mt][0] = __float_as_uint(As[buf][am + r    ][ks + c    ]);
                af[mt][1] = __float_as_uint(As[buf][am + r + 8][ks + c    ]);
                af[mt][2] = __float_as_uint(As[buf][am + r    ][ks + c + 4]);
                af[mt][3] = __float_as_uint(As[buf][am + r + 8][ks + c + 4]);
            }
            #pragma unroll
            for (int nt = 0; nt < 8; nt++) {
                int bn = wn * 64 + nt * 8;
                bf[nt][0] = __float_as_uint(Bs[buf][ks + c    ][bn + r]);
                bf[nt][1] = __float_as_uint(Bs[buf][ks + c + 4][bn + r]);
            }
            #pragma unroll
            for (int mt = 0; mt < 4; mt++)
                #pragma unroll
                for (int nt = 0; nt < 8; nt++)
                    mma_tf32(acc[mt][nt], af[mt], bf[nt]);
        }
        buf++; if (buf == GSTAGES) buf = 0;
    }

    // ---- epilogue ----
    #pragma unroll
    for (int mt = 0; mt < 4; mt++) {
        #pragma unroll
        for (int nt = 0; nt < 8; nt++) {
            int col = n0 + wn * 64 + nt * 8 + 2 * c;
            #pragma unroll
            for (int half = 0; half < 2; half++) {
                size_t row = (size_t)(m0 + wm * 64 + mt * 16 + r + half * 8);
                float x0 = acc[mt][nt][half * 2 + 0];
                float x1 = acc[mt][nt][half * 2 + 1];
                if (EPI == 1) {
                    x0 += bias[col];
                    x1 += bias[col + 1];
                    x0 = tf32r(0.5f * x0 * (1.0f + erff(x0 * 0.70710678118654752f)));
                    x1 = tf32r(0.5f * x1 * (1.0f + erff(x1 * 0.70710678118654752f)));
                } else if (EPI == 2) {
                    x0 += bias[col]     + res[row * N + col];
                    x1 += bias[col + 1] + res[row * N + col + 1];
                } else if (EPI == 3) {
                    x0 = tf32r(x0);
                    x1 = tf32r(x1);
                }
                float2 v; v.x = x0; v.y = x1;
                *(float2*)&C[row * N + col] = v;
            }
        }
    }
}

// =====================================================================
// RoPE — reference indexes sin/cos by BATCH index (L = x.shape[0] = B).
// Output tf32-rounded so attention can cp.async K/V raw.
// =====================================================================
__global__ void __launch_bounds__(256) rope_kernel(
    float* __restrict__ x, const float* __restrict__ sinp,
    const float* __restrict__ cosp)
{
    __shared__ float row[DIM];
    const int r = blockIdx.x;
    const int b = r / SEQ;
    const size_t base = (size_t)r * DIM;
    for (int i = threadIdx.x; i < DIM/4; i += 256)
        *(float4*)&row[i * 4] = *(const float4*)&x[base + i * 4];
    __syncthreads();
    for (int j = threadIdx.x; j < DIM/2; j += 256) {
        float x1 = row[2*j], x2 = row[2*j + 1];
        float c = cosp[b * (DIM/2) + j];
        float s = sinp[b * (DIM/2) + j];
        x[base + j]           = tf32r(x1 * c - x2 * s);
        x[base + (DIM/2) + j] = tf32r(x1 * s + x2 * c);
    }
}

// =====================================================================
// Tensor-core flash attention, double-buffered cp.async K/V,
// Q fragments register-resident. BM=128 q-rows, BN=64 kv, 8 warps.
// K/V are already tf32-clean (rope / EPI3 outputs) -> raw cp.async ok.
// =====================================================================
#define KP2 132
#define VP2 136
#define PP2 68
#define ATT_SMEM ((2*64*KP2 + 2*64*VP2 + 128*PP2) * 4)   // 172032 B

__global__ void __launch_bounds__(256, 1) attn_mma_kernel()
{
    extern __shared__ float sm[];
    float* Ks = sm;                     // 2 stages x 64 x KP2 (also Q staging temp)
    float* Vs = Ks + 2 * 64 * KP2;      // 2 stages x 64 x VP2
    float* Ps = Vs + 2 * 64 * VP2;      // 128 x PP2

    const int qb = (gridDim.x - 1) - blockIdx.x;  // heavy blocks first
    const int h = blockIdx.y, b = blockIdx.z;
    const int tid = threadIdx.x;
    const int w = tid >> 5, lane = tid & 31;
    const int grp = lane >> 2, c = lane & 3;
    const float scale = 0.08838834764831845f;  // 1/sqrt(128)

    // ---- stage Q (128x128) into Ks region, scale + round; then to regs ----
    const size_t qbase = ((size_t)(b * SEQ + qb * 128)) * DIM + h * HD;
    for (int idx = tid; idx < 128 * 32; idx += 256) {
        int r = idx >> 5, c4 = (idx & 31) << 2;
        float4 v = *(const float4*)&g_q[qbase + (size_t)r * DIM + c4];
        v.x = tf32r(v.x * scale); v.y = tf32r(v.y * scale);
        v.z = tf32r(v.z * scale); v.w = tf32r(v.w * scale);
        *(float4*)&Ks[r * KP2 + c4] = v;
    }
    __syncthreads();

    uint32_t qf[16][4];
    {
        const int row0 = (w * 16 + grp) * KP2;
        const int row1 = row0 + 8 * KP2;
        #pragma unroll
        for (int dd = 0; dd < 16; dd++) {
            qf[dd][0] = __float_as_uint(Ks[row0 + dd*8 + c    ]);
            qf[dd][1] = __float_as_uint(Ks[row1 + dd*8 + c    ]);
            qf[dd][2] = __float_as_uint(Ks[row0 + dd*8 + c + 4]);
            qf[dd][3] = __float_as_uint(Ks[row1 + dd*8 + c + 4]);
        }
    }
    __syncthreads();   // Q regs loaded before K prefetch overwrites region

    const int krow = tid >> 5, kcol = (tid & 31) * 4;
    auto issue_kv = [&](int kt, int st) {
        const size_t kb = ((size_t)(b * SEQ + kt * 64)) * DIM + h * HD;
        float* Kd = Ks + st * 64 * KP2;
        float* Vd = Vs + st * 64 * VP2;
        #pragma unroll
        for (int i = 0; i < 8; i++) {
            int rr = krow + 8 * i;
            cp16(&Kd[rr * KP2 + kcol], &g_k[kb + (size_t)rr * DIM + kcol]);
            cp16(&Vd[rr * VP2 + kcol], &g_v[kb + (size_t)rr * DIM + kcol]);
        }
        asm volatile("cp.async.commit_group;\n");
    };

    float o[16][4];
    #pragma unroll
    for (int nt = 0; nt < 16; nt++)
        #pragma unroll
        for (int i = 0; i < 4; i++) o[nt][i] = 0.f;
    float m0v = -1e30f, m1v = -1e30f, l0 = 0.f, l1 = 0.f;

    const int rowg0 = qb * 128 + w * 16 + grp;
    const int rowg1 = rowg0 + 8;
    const int ktiles = 2 * qb + 2;

    issue_kv(0, 0);

    for (int kt = 0; kt < ktiles; kt++) {
        if (kt + 1 < ktiles) issue_kv(kt + 1, (kt + 1) & 1);
        else                 asm volatile("cp.async.commit_group;\n");
        asm volatile("cp.async.wait_group 1;\n");
        __syncthreads();   // all threads see tile kt

        const int st = kt & 1;
        const float* Kst = Ks + st * 64 * KP2;
        const float* Vst = Vs + st * 64 * VP2;

        // ---- S = Q K^T ----
        float sacc[8][4];
        #pragma unroll
        for (int nt = 0; nt < 8; nt++)
            #pragma unroll
            for (int i = 0; i < 4; i++) sacc[nt][i] = 0.f;

        #pragma unroll
        for (int dd = 0; dd < 16; dd++) {
            #pragma unroll
            for (int nt = 0; nt < 8; nt++) {
                uint32_t bf[2];
                bf[0] = __float_as_uint(Kst[(nt*8 + grp) * KP2 + dd*8 + c    ]);
                bf[1] = __float_as_uint(Kst[(nt*8 + grp) * KP2 + dd*8 + c + 4]);
                mma_tf32(sacc[nt], qf[dd], bf);
            }
        }

        // causal mask (only possible on the last two tiles)
        if (kt >= 2 * qb) {
            #pragma unroll
            for (int nt = 0; nt < 8; nt++) {
                int colg = kt * 64 + nt * 8 + 2 * c;
                if (colg     > rowg0) sacc[nt][0] = -1e30f;
                if (colg + 1 > rowg0) sacc[nt][1] = -1e30f;
                if (colg     > rowg1) sacc[nt][2] = -1e30f;
                if (colg + 1 > rowg1) sacc[nt][3] = -1e30f;
            }
        }

        // ---- online softmax (rows grp and grp+8, warp-local) ----
        float mx0 = -1e30f, mx1 = -1e30f;
        #pragma unroll
        for (int nt = 0; nt < 8; nt++) {
            mx0 = fmaxf(mx0, fmaxf(sacc[nt][0], sacc[nt][1]));
            mx1 = fmaxf(mx1, fmaxf(sacc[nt][2], sacc[nt][3]));
        }
        mx0 = fmaxf(mx0, __shfl_xor_sync(0xffffffffu, mx0, 1));
        mx0 = fmaxf(mx0, __shfl_xor_sync(0xffffffffu, mx0, 2));
        mx1 = fmaxf(mx1, __shfl_xor_sync(0xffffffffu, mx1, 1));
        mx1 = fmaxf(mx1, __shfl_xor_sync(0xffffffffu, mx1, 2));
        float mn0 = fmaxf(m0v, mx0), mn1 = fmaxf(m1v, mx1);
        float a0 = __expf(m0v - mn0), a1 = __expf(m1v - mn1);

        float s0 = 0.f, s1 = 0.f;
        #pragma unroll
        for (int nt = 0; nt < 8; nt++) {
            float p00 = tf32r(__expf(sacc[nt][0] - mn0));
            float p01 = tf32r(__expf(sacc[nt][1] - mn0));
            float p10 = tf32r(__expf(sacc[nt][2] - mn1));
            float p11 = tf32r(__expf(sacc[nt][3] - mn1));
            s0 += p00 + p01; s1 += p10 + p11;
            float2 e0; e0.x = p00; e0.y = p01;
            float2 e1; e1.x = p10; e1.y = p11;
            *(float2*)&Ps[(w*16 + grp    ) * PP2 + nt*8 + 2*c] = e0;
            *(float2*)&Ps[(w*16 + grp + 8) * PP2 + nt*8 + 2*c] = e1;
        }
        s0 += __shfl_xor_sync(0xffffffffu, s0, 1);
        s0 += __shfl_xor_sync(0xffffffffu, s0, 2);
        s1 += __shfl_xor_sync(0xffffffffu, s1, 1);
        s1 += __shfl_xor_sync(0xffffffffu, s1, 2);
        l0 = l0 * a0 + s0;
        l1 = l1 * a1 + s1;
        m0v = mn0; m1v = mn1;
        #pragma unroll
        for (int nt = 0; nt < 16; nt++) {
            o[nt][0] *= a0; o[nt][1] *= a0;
            o[nt][2] *= a1; o[nt][3] *= a1;
        }
        __syncwarp();   // P written by this warp is read by this warp only

        // ---- O += P @ V ----
        #pragma unroll
        for (int kk = 0; kk < 8; kk++) {
            uint32_t af2[4];
            af2[0] = __float_as_uint(Ps[(w*16 + grp    ) * PP2 + kk*8 + c    ]);
            af2[1] = __float_as_uint(Ps[(w*16 + grp + 8) * PP2 + kk*8 + c    ]);
            af2[2] = __float_as_uint(Ps[(w*16 + grp    ) * PP2 + kk*8 + c + 4]);
            af2[3] = __float_as_uint(Ps[(w*16 + grp + 8) * PP2 + kk*8 + c + 4]);
            #pragma unroll
            for (int nt = 0; nt < 16; nt++) {
                uint32_t bf2[2];
                bf2[0] = __float_as_uint(Vst[(kk*8 + c    ) * VP2 + nt*8 + grp]);
                bf2[1] = __float_as_uint(Vst[(kk*8 + c + 4) * VP2 + nt*8 + grp]);
                mma_tf32(o[nt], af2, bf2);
            }
        }
        __syncthreads();   // stage kt&1 fully consumed before next overwrite
    }

    // ---- writeout ----
    float inv0 = 1.0f / l0, inv1 = 1.0f / l1;
    size_t grow0 = (size_t)(b * SEQ + qb * 128 + w * 16 + grp);
    size_t grow1 = grow0 + 8;
    #pragma unroll
    for (int nt = 0; nt < 16; nt++) {
        int col = h * HD + nt * 8 + 2 * c;
        float2 v0; v0.x = o[nt][0] * inv0; v0.y = o[nt][1] * inv0;
        float2 v1; v1.x = o[nt][2] * inv1; v1.y = o[nt][3] * inv1;
        *(float2*)&g_attn[grow0 * DIM + col] = v0;
        *(float2*)&g_attn[grow1 * DIM + col] = v1;
    }
}

// =====================================================================
// LayerNorm over last dim (2048). Biased variance. Optional residual add
// and optional second tf32-rounded output (for GEMM A-operand).
// =====================================================================
template<bool ADDX, bool T32OUT>
__global__ void __launch_bounds__(256) ln_kernel(
    const float* __restrict__ in, const float* __restrict__ add,
    float* __restrict__ out, float* __restrict__ out_t)
{
    __shared__ float redS[8], redQ[8];
    const int tid = threadIdx.x;
    const size_t base = (size_t)blockIdx.x * DIM;
    float v[8];
    float s = 0.f, q = 0.f;
    #pragma unroll
    for (int k = 0; k < 8; k++) {
        float a = in[base + tid + k*256];
        if (ADDX) a += add[base + tid + k*256];
        v[k] = a; s += a; q += a * a;
    }
    #pragma unroll
    for (int d = 16; d >= 1; d >>= 1) {
        s += __shfl_xor_sync(0xffffffffu, s, d);
        q += __shfl_xor_sync(0xffffffffu, q, d);
    }
    if ((tid & 31) == 0) { redS[tid >> 5] = s; redQ[tid >> 5] = q; }
    __syncthreads();
    float ts = 0.f, tq = 0.f;
    #pragma unroll
    for (int wv = 0; wv < 8; wv++) { ts += redS[wv]; tq += redQ[wv]; }
    float mean = ts * (1.f / DIM);
    float var  = tq * (1.f / DIM) - mean * mean;
    float rstd = rsqrtf(var + 1e-5f);
    #pragma unroll
    for (int k = 0; k < 8; k++) {
        float y = (v[k] - mean) * rstd;
        out[base + tid + k*256] = y;
        if (T32OUT) out_t[base + tid + k*256] = tf32r(y);
    }
}

// =====================================================================
extern "C" void kernel_launch(void* const* d_in, const int* in_sizes, int n_in,
                              void* d_out, int out_size)
{
    const float* x    = (const float*)d_in[0];
    const float* Wq   = (const float*)d_in[1];
    const float* Wk   = (const float*)d_in[2];
    const float* Wv   = (const float*)d_in[3];
    const float* W1   = (const float*)d_in[4];
    const float* b1   = (const float*)d_in[5];
    const float* W2   = (const float*)d_in[6];
    const float* b2   = (const float*)d_in[7];
    const float* sinp = (const float*)d_in[8];
    const float* cosp = (const float*)d_in[9];
    float* out = (float*)d_out;

    float *q, *k, *v, *attn, *ln1, *hbuf;
    float *xt, *wqt, *wkt, *wvt, *w1t, *w2t, *ln1t;
    cudaGetSymbolAddress((void**)&q,    g_q);
    cudaGetSymbolAddress((void**)&k,    g_k);
    cudaGetSymbolAddress((void**)&v,    g_v);
    cudaGetSymbolAddress((void**)&attn, g_attn);
    cudaGetSymbolAddress((void**)&ln1,  g_ln1);
    cudaGetSymbolAddress((void**)&hbuf, g_h);
    cudaGetSymbolAddress((void**)&xt,   g_xt);
    cudaGetSymbolAddress((void**)&wqt,  g_wqt);
    cudaGetSymbolAddress((void**)&wkt,  g_wkt);
    cudaGetSymbolAddress((void**)&wvt,  g_wvt);
    cudaGetSymbolAddress((void**)&w1t,  g_w1t);
    cudaGetSymbolAddress((void**)&w2t,  g_w2t);
    cudaGetSymbolAddress((void**)&ln1t, g_ln1t);

    cudaFuncSetAttribute(gemm_tc<0>, cudaFuncAttributeMaxDynamicSharedMemorySize, GSMEM_BYTES);
    cudaFuncSetAttribute(gemm_tc<1>, cudaFuncAttributeMaxDynamicSharedMemorySize, GSMEM_BYTES);
    cudaFuncSetAttribute(gemm_tc<2>, cudaFuncAttributeMaxDynamicSharedMemorySize, GSMEM_BYTES);
    cudaFuncSetAttribute(gemm_tc<3>, cudaFuncAttributeMaxDynamicSharedMemorySize, GSMEM_BYTES);
    cudaFuncSetAttribute(attn_mma_kernel, cudaFuncAttributeMaxDynamicSharedMemorySize, ATT_SMEM);

    const dim3 thr(256);
    const dim3 gthr(128);

    // operand prep (x, Wq, Wk, Wv only — W1/W2 later so launch #5 is a GEMM
    // and ncu's "-s 5 -c 1" captures it)
    cvt_tf32_kernel<<<2048, thr>>>(x,  xt,  ((size_t)MROWS*DIM)/4);
    cvt_tf32_kernel<<<2048, thr>>>(Wq, wqt, ((size_t)DIM*DIM)/4);
    cvt_tf32_kernel<<<2048, thr>>>(Wk, wkt, ((size_t)DIM*DIM)/4);
    cvt_tf32_kernel<<<2048, thr>>>(Wv, wvt, ((size_t)DIM*DIM)/4);

    // QKV projections (V output tf32-rounded for raw cp.async in attention)
    gemm_tc<0><<<dim3(DIM/128, MROWS/128), gthr, GSMEM_BYTES>>>(xt, wqt, q, nullptr, nullptr, DIM, DIM);
    gemm_tc<0><<<dim3(DIM/128, MROWS/128), gthr, GSMEM_BYTES>>>(xt, wkt, k, nullptr, nullptr, DIM, DIM);
    gemm_tc<3><<<dim3(DIM/128, MROWS/128), gthr, GSMEM_BYTES>>>(xt, wvt, v, nullptr, nullptr, DIM, DIM);

    // RoPE (batch-indexed sin/cos — reference quirk); outputs tf32-rounded
    rope_kernel<<<MROWS, thr>>>(q, sinp, cosp);
    rope_kernel<<<MROWS, thr>>>(k, sinp, cosp);

    // remaining weight prep (overlaps conceptually; needed before MLP)
    cvt_tf32_kernel<<<2048, thr>>>(W1, w1t, ((size_t)DIM*DFF)/4);
    cvt_tf32_kernel<<<2048, thr>>>(W2, w2t, ((size_t)DFF*DIM)/4);

    // Tensor-core causal flash attention (double-buffered K/V)
    attn_mma_kernel<<<dim3(SEQ/128, NH, BATCH), thr, ATT_SMEM>>>();

    // LN1 with residual (fp32 out for residual; tf32 copy for MLP1 A)
    ln_kernel<true, true><<<MROWS, thr>>>(attn, x, ln1, ln1t);

    // MLP
    gemm_tc<1><<<dim3(DFF/128, MROWS/128), gthr, GSMEM_BYTES>>>(ln1t, w1t, hbuf, b1, nullptr, DFF, DIM);
    gemm_tc<2><<<dim3(DIM/128, MROWS/128), gthr, GSMEM_BYTES>>>(hbuf, w2t, q, b2, ln1, DIM, DFF);

    // LN2 -> output
    ln_kernel<false, false><<<MROWS, thr>>>(q, nullptr, out, nullptr);
}

// round 8
// speedup vs baseline: 5.8567x; 1.4602x over previous
#include <cuda_runtime.h>
#include <cuda_fp16.h>
#include <cstdint>

#define BATCH 2
#define SEQ   2048
#define DIM   2048
#define NH    16
#define HD    128
#define MROWS (BATCH*SEQ)   // 4096
#define DFF   8192

// ---- scratch (allocation-free rule: __device__ globals) ----
__device__ float g_q[(size_t)MROWS * DIM];
__device__ float g_k[(size_t)MROWS * DIM];
__device__ float g_v[(size_t)MROWS * DIM];
__device__ float g_attn[(size_t)MROWS * DIM];
__device__ float g_ln1[(size_t)MROWS * DIM];
// fp16 operands
__device__ __half g_xh [(size_t)MROWS * DIM];
__device__ __half g_wqh[(size_t)DIM * DIM];    // [N][K] transposed
__device__ __half g_wkh[(size_t)DIM * DIM];
__device__ __half g_wvh[(size_t)DIM * DIM];
__device__ __half g_w1h[(size_t)DFF * DIM];    // [8192][2048]
__device__ __half g_w2h[(size_t)DIM * DFF];    // [2048][8192]
__device__ __half g_ln1h[(size_t)MROWS * DIM];
__device__ __half g_h  [(size_t)MROWS * DFF];  // gelu output, fp16

// =====================================================================
// helpers
// =====================================================================
__device__ __forceinline__ float tf32r(float x) {
    float r;
    asm("cvt.rna.tf32.f32 %0, %1;" : "=f"(r) : "f"(x));
    return r;
}

__device__ __forceinline__ void mma_tf32(float (&d)[4],
                                         const uint32_t (&a)[4],
                                         const uint32_t (&b)[2]) {
    asm volatile(
        "mma.sync.aligned.m16n8k8.row.col.f32.tf32.tf32.f32 "
        "{%0,%1,%2,%3}, {%4,%5,%6,%7}, {%8,%9}, {%0,%1,%2,%3};"
        : "+f"(d[0]), "+f"(d[1]), "+f"(d[2]), "+f"(d[3])
        : "r"(a[0]), "r"(a[1]), "r"(a[2]), "r"(a[3]),
          "r"(b[0]), "r"(b[1]));
}

__device__ __forceinline__ void mma_f16(float (&d)[4],
                                        const uint32_t (&a)[4],
                                        const uint32_t (&b)[2]) {
    asm volatile(
        "mma.sync.aligned.m16n8k16.row.col.f32.f16.f16.f32 "
        "{%0,%1,%2,%3}, {%4,%5,%6,%7}, {%8,%9}, {%0,%1,%2,%3};"
        : "+f"(d[0]), "+f"(d[1]), "+f"(d[2]), "+f"(d[3])
        : "r"(a[0]), "r"(a[1]), "r"(a[2]), "r"(a[3]),
          "r"(b[0]), "r"(b[1]));
}

__device__ __forceinline__ void cp16(void* sdst, const void* gsrc) {
    uint32_t s = (uint32_t)__cvta_generic_to_shared(sdst);
    asm volatile("cp.async.cg.shared.global [%0], [%1], 16;\n" :: "r"(s), "l"(gsrc));
}

__device__ __forceinline__ void store2(float* C, size_t idx, float x0, float x1) {
    float2 v; v.x = x0; v.y = x1;
    *(float2*)&C[idx] = v;
}
__device__ __forceinline__ void store2(__half* C, size_t idx, float x0, float x1) {
    *(__half2*)&C[idx] = __floats2half2_rn(x0, x1);
}

// fp32 -> fp16 elementwise (float4 grid-stride)
__global__ void __launch_bounds__(256) cvt_f16_kernel(
    const float* __restrict__ in, __half* __restrict__ out, size_t n4)
{
    size_t stride = (size_t)gridDim.x * blockDim.x;
    for (size_t i = (size_t)blockIdx.x * blockDim.x + threadIdx.x; i < n4; i += stride) {
        float4 v = ((const float4*)in)[i];
        __half2 h01 = __floats2half2_rn(v.x, v.y);
        __half2 h23 = __floats2half2_rn(v.z, v.w);
        uint2 u;
        u.x = *reinterpret_cast<uint32_t*>(&h01);
        u.y = *reinterpret_cast<uint32_t*>(&h23);
        *(uint2*)(out + i * 4) = u;
    }
}

// fp32 [K][N] -> fp16 transposed [N][K]
__global__ void __launch_bounds__(256) twf16_kernel(
    const float* __restrict__ in, __half* __restrict__ out, int K, int N)
{
    __shared__ __half tile[32][33];
    const int n0 = blockIdx.x * 32, k0 = blockIdx.y * 32;
    const int tx = threadIdx.x & 31, ty = threadIdx.x >> 5;  // 32 x 8
    #pragma unroll
    for (int i = 0; i < 4; i++)
        tile[ty + i * 8][tx] = __float2half_rn(in[(size_t)(k0 + ty + i * 8) * N + n0 + tx]);
    __syncthreads();
    #pragma unroll
    for (int i = 0; i < 4; i++)
        out[(size_t)(n0 + ty + i * 8) * K + k0 + tx] = tile[tx][ty + i * 8];
}

// =====================================================================
// fp16 tensor-core GEMM: C[M,N] = A[M,K] @ Bt[N,K]^T
// 128 threads (4 warps 2x2), block 128x128, warp 64x64, K-tile 32,
// 3-stage cp.async, mma.m16n8k16. Smem pitch 40 halves (80B):
// cp.async dst 16B-aligned; fragment LDS banks 20g+c mod 32 all distinct.
// EPI 0: none | 1: +bias exact GELU (half out) | 2: +bias +res | 3: tf32 round
// =====================================================================
#define GSTAGES 3
#define GSMEM_BYTES (GSTAGES * (128*40 + 128*40) * 2)

template<int EPI, typename CT>
__global__ void __launch_bounds__(128, 2) gemm_f16(
    const __half* __restrict__ A, const __half* __restrict__ Bt,
    CT* __restrict__ C, const float* __restrict__ bias,
    const float* __restrict__ res, int N, int K)
{
    extern __shared__ __half shh[];
    __half (*As)[128][40] = (__half(*)[128][40])shh;
    __half (*Bs)[128][40] = (__half(*)[128][40])(shh + GSTAGES * 128 * 40);

    const int tid  = threadIdx.x;
    const int warp = tid >> 5, lane = tid & 31;
    const int wm = warp >> 1;          // 0..1
    const int wn = warp & 1;           // 0..1
    const int g  = lane >> 2;          // 0..7
    const int c  = lane & 3;           // 0..3
    const int m0 = blockIdx.y * 128, n0 = blockIdx.x * 128;

    const int srow = tid >> 2;            // 0..31
    const int scol = (tid & 3) * 8;       // 0,8,16,24

    const int T = K >> 5;

    auto issue_tile = [&](int t, int buf) {
        #pragma unroll
        for (int i = 0; i < 4; i++)
            cp16(&As[buf][srow + i*32][scol],
                 A + (size_t)(m0 + srow + i*32) * K + t*32 + scol);
        #pragma unroll
        for (int i = 0; i < 4; i++)
            cp16(&Bs[buf][srow + i*32][scol],
                 Bt + (size_t)(n0 + srow + i*32) * K + t*32 + scol);
        asm volatile("cp.async.commit_group;\n");
    };

    float acc[4][8][4];
    #pragma unroll
    for (int mt = 0; mt < 4; mt++)
        #pragma unroll
        for (int nt = 0; nt < 8; nt++)
            #pragma unroll
            for (int i = 0; i < 4; i++) acc[mt][nt][i] = 0.f;

    issue_tile(0, 0);
    issue_tile(1, 1);

    int buf = 0;
    for (int t = 0; t < T; t++) {
        asm volatile("cp.async.wait_group 1;\n");
        __syncthreads();
        if (t + 2 < T) {
            int nb = buf + 2; if (nb >= GSTAGES) nb -= GSTAGES;
            issue_tile(t + 2, nb);
        } else {
            asm volatile("cp.async.commit_group;\n");
        }

        #pragma unroll
        for (int ks = 0; ks < 32; ks += 16) {
            uint32_t af[4][4];
            uint32_t bf[8][2];
            #pragma unroll
            for (int mt = 0; mt < 4; mt++) {
                int am = wm * 64 + mt * 16;
                af[mt][0] = *(const uint32_t*)&As[buf][am + g    ][ks + 2*c    ];
                af[mt][1] = *(const uint32_t*)&As[buf][am + g + 8][ks + 2*c    ];
                af[mt][2] = *(const uint32_t*)&As[buf][am + g    ][ks + 2*c + 8];
                af[mt][3] = *(const uint32_t*)&As[buf][am + g + 8][ks + 2*c + 8];
            }
            #pragma unroll
            for (int nt = 0; nt < 8; nt++) {
                int bn = wn * 64 + nt * 8;
                bf[nt][0] = *(const uint32_t*)&Bs[buf][bn + g][ks + 2*c    ];
                bf[nt][1] = *(const uint32_t*)&Bs[buf][bn + g][ks + 2*c + 8];
            }
            #pragma unroll
            for (int mt = 0; mt < 4; mt++)
                #pragma unroll
                for (int nt = 0; nt < 8; nt++)
                    mma_f16(acc[mt][nt], af[mt], bf[nt]);
        }
        buf++; if (buf == GSTAGES) buf = 0;
    }

    // ---- epilogue ----
    #pragma unroll
    for (int mt = 0; mt < 4; mt++) {
        #pragma unroll
        for (int nt = 0; nt < 8; nt++) {
            int col = n0 + wn * 64 + nt * 8 + 2 * c;
            #pragma unroll
            for (int half_ = 0; half_ < 2; half_++) {
                size_t row = (size_t)(m0 + wm * 64 + mt * 16 + g + half_ * 8);
                float x0 = acc[mt][nt][half_ * 2 + 0];
                float x1 = acc[mt][nt][half_ * 2 + 1];
                if (EPI == 1) {
                    x0 += bias[col];
                    x1 += bias[col + 1];
                    x0 = 0.5f * x0 * (1.0f + erff(x0 * 0.70710678118654752f));
                    x1 = 0.5f * x1 * (1.0f + erff(x1 * 0.70710678118654752f));
                } else if (EPI == 2) {
                    x0 += bias[col]     + res[row * N + col];
                    x1 += bias[col + 1] + res[row * N + col + 1];
                } else if (EPI == 3) {
                    x0 = tf32r(x0);
                    x1 = tf32r(x1);
                }
                store2(C, row * N + col, x0, x1);
            }
        }
    }
}

// =====================================================================
// RoPE — reference indexes sin/cos by BATCH index (L = x.shape[0] = B).
// Output tf32-rounded so attention can cp.async K/V raw.
// =====================================================================
__global__ void __launch_bounds__(256) rope_kernel(
    float* __restrict__ x, const float* __restrict__ sinp,
    const float* __restrict__ cosp)
{
    __shared__ float row[DIM];
    const int r = blockIdx.x;
    const int b = r / SEQ;
    const size_t base = (size_t)r * DIM;
    for (int i = threadIdx.x; i < DIM/4; i += 256)
        *(float4*)&row[i * 4] = *(const float4*)&x[base + i * 4];
    __syncthreads();
    for (int j = threadIdx.x; j < DIM/2; j += 256) {
        float x1 = row[2*j], x2 = row[2*j + 1];
        float c = cosp[b * (DIM/2) + j];
        float s = sinp[b * (DIM/2) + j];
        x[base + j]           = tf32r(x1 * c - x2 * s);
        x[base + (DIM/2) + j] = tf32r(x1 * s + x2 * c);
    }
}

// =====================================================================
// Tensor-core flash attention (tf32), double-buffered cp.async K/V,
// Q fragments register-resident. BM=128 q-rows, BN=64 kv, 8 warps.
// (unchanged from R7 — passing, rel_err-verified)
// =====================================================================
#define KP2 132
#define VP2 136
#define PP2 68
#define ATT_SMEM ((2*64*KP2 + 2*64*VP2 + 128*PP2) * 4)   // 172032 B

__global__ void __launch_bounds__(256, 1) attn_mma_kernel()
{
    extern __shared__ float sm[];
    float* Ks = sm;
    float* Vs = Ks + 2 * 64 * KP2;
    float* Ps = Vs + 2 * 64 * VP2;

    const int qb = (gridDim.x - 1) - blockIdx.x;
    const int h = blockIdx.y, b = blockIdx.z;
    const int tid = threadIdx.x;
    const int w = tid >> 5, lane = tid & 31;
    const int grp = lane >> 2, c = lane & 3;
    const float scale = 0.08838834764831845f;

    const size_t qbase = ((size_t)(b * SEQ + qb * 128)) * DIM + h * HD;
    for (int idx = tid; idx < 128 * 32; idx += 256) {
        int r = idx >> 5, c4 = (idx & 31) << 2;
        float4 v = *(const float4*)&g_q[qbase + (size_t)r * DIM + c4];
        v.x = tf32r(v.x * scale); v.y = tf32r(v.y * scale);
        v.z = tf32r(v.z * scale); v.w = tf32r(v.w * scale);
        *(float4*)&Ks[r * KP2 + c4] = v;
    }
    __syncthreads();

    uint32_t qf[16][4];
    {
        const int row0 = (w * 16 + grp) * KP2;
        const int row1 = row0 + 8 * KP2;
        #pragma unroll
        for (int dd = 0; dd < 16; dd++) {
            qf[dd][0] = __float_as_uint(Ks[row0 + dd*8 + c    ]);
            qf[dd][1] = __float_as_uint(Ks[row1 + dd*8 + c    ]);
            qf[dd][2] = __float_as_uint(Ks[row0 + dd*8 + c + 4]);
            qf[dd][3] = __float_as_uint(Ks[row1 + dd*8 + c + 4]);
        }
    }
    __syncthreads();

    const int krow = tid >> 5, kcol = (tid & 31) * 4;
    auto issue_kv = [&](int kt, int st) {
        const size_t kb = ((size_t)(b * SEQ + kt * 64)) * DIM + h * HD;
        float* Kd = Ks + st * 64 * KP2;
        float* Vd = Vs + st * 64 * VP2;
        #pragma unroll
        for (int i = 0; i < 8; i++) {
            int rr = krow + 8 * i;
            cp16(&Kd[rr * KP2 + kcol], &g_k[kb + (size_t)rr * DIM + kcol]);
            cp16(&Vd[rr * VP2 + kcol], &g_v[kb + (size_t)rr * DIM + kcol]);
        }
        asm volatile("cp.async.commit_group;\n");
    };

    float o[16][4];
    #pragma unroll
    for (int nt = 0; nt < 16; nt++)
        #pragma unroll
        for (int i = 0; i < 4; i++) o[nt][i] = 0.f;
    float m0v = -1e30f, m1v = -1e30f, l0 = 0.f, l1 = 0.f;

    const int rowg0 = qb * 128 + w * 16 + grp;
    const int rowg1 = rowg0 + 8;
    const int ktiles = 2 * qb + 2;

    issue_kv(0, 0);

    for (int kt = 0; kt < ktiles; kt++) {
        if (kt + 1 < ktiles) issue_kv(kt + 1, (kt + 1) & 1);
        else                 asm volatile("cp.async.commit_group;\n");
        asm volatile("cp.async.wait_group 1;\n");
        __syncthreads();

        const int st = kt & 1;
        const float* Kst = Ks + st * 64 * KP2;
        const float* Vst = Vs + st * 64 * VP2;

        float sacc[8][4];
        #pragma unroll
        for (int nt = 0; nt < 8; nt++)
            #pragma unroll
            for (int i = 0; i < 4; i++) sacc[nt][i] = 0.f;

        #pragma unroll
        for (int dd = 0; dd < 16; dd++) {
            #pragma unroll
            for (int nt = 0; nt < 8; nt++) {
                uint32_t bf[2];
                bf[0] = __float_as_uint(Kst[(nt*8 + grp) * KP2 + dd*8 + c    ]);
                bf[1] = __float_as_uint(Kst[(nt*8 + grp) * KP2 + dd*8 + c + 4]);
                mma_tf32(sacc[nt], qf[dd], bf);
            }
        }

        if (kt >= 2 * qb) {
            #pragma unroll
            for (int nt = 0; nt < 8; nt++) {
                int colg = kt * 64 + nt * 8 + 2 * c;
                if (colg     > rowg0) sacc[nt][0] = -1e30f;
                if (colg + 1 > rowg0) sacc[nt][1] = -1e30f;
                if (colg     > rowg1) sacc[nt][2] = -1e30f;
                if (colg + 1 > rowg1) sacc[nt][3] = -1e30f;
            }
        }

        float mx0 = -1e30f, mx1 = -1e30f;
        #pragma unroll
        for (int nt = 0; nt < 8; nt++) {
            mx0 = fmaxf(mx0, fmaxf(sacc[nt][0], sacc[nt][1]));
            mx1 = fmaxf(mx1, fmaxf(sacc[nt][2], sacc[nt][3]));
        }
        mx0 = fmaxf(mx0, __shfl_xor_sync(0xffffffffu, mx0, 1));
        mx0 = fmaxf(mx0, __shfl_xor_sync(0xffffffffu, mx0, 2));
        mx1 = fmaxf(mx1, __shfl_xor_sync(0xffffffffu, mx1, 1));
        mx1 = fmaxf(mx1, __shfl_xor_sync(0xffffffffu, mx1, 2));
        float mn0 = fmaxf(m0v, mx0), mn1 = fmaxf(m1v, mx1);
        float a0 = __expf(m0v - mn0), a1 = __expf(m1v - mn1);

        float s0 = 0.f, s1 = 0.f;
        #pragma unroll
        for (int nt = 0; nt < 8; nt++) {
            float p00 = tf32r(__expf(sacc[nt][0] - mn0));
            float p01 = tf32r(__expf(sacc[nt][1] - mn0));
            float p10 = tf32r(__expf(sacc[nt][2] - mn1));
            float p11 = tf32r(__expf(sacc[nt][3] - mn1));
            s0 += p00 + p01; s1 += p10 + p11;
            float2 e0; e0.x = p00; e0.y = p01;
            float2 e1; e1.x = p10; e1.y = p11;
            *(float2*)&Ps[(w*16 + grp    ) * PP2 + nt*8 + 2*c] = e0;
            *(float2*)&Ps[(w*16 + grp + 8) * PP2 + nt*8 + 2*c] = e1;
        }
        s0 += __shfl_xor_sync(0xffffffffu, s0, 1);
        s0 += __shfl_xor_sync(0xffffffffu, s0, 2);
        s1 += __shfl_xor_sync(0xffffffffu, s1, 1);
        s1 += __shfl_xor_sync(0xffffffffu, s1, 2);
        l0 = l0 * a0 + s0;
        l1 = l1 * a1 + s1;
        m0v = mn0; m1v = mn1;
        #pragma unroll
        for (int nt = 0; nt < 16; nt++) {
            o[nt][0] *= a0; o[nt][1] *= a0;
            o[nt][2] *= a1; o[nt][3] *= a1;
        }
        __syncwarp();

        #pragma unroll
        for (int kk = 0; kk < 8; kk++) {
            uint32_t af2[4];
            af2[0] = __float_as_uint(Ps[(w*16 + grp    ) * PP2 + kk*8 + c    ]);
            af2[1] = __float_as_uint(Ps[(w*16 + grp + 8) * PP2 + kk*8 + c    ]);
            af2[2] = __float_as_uint(Ps[(w*16 + grp    ) * PP2 + kk*8 + c + 4]);
            af2[3] = __float_as_uint(Ps[(w*16 + grp + 8) * PP2 + kk*8 + c + 4]);
            #pragma unroll
            for (int nt = 0; nt < 16; nt++) {
                uint32_t bf2[2];
                bf2[0] = __float_as_uint(Vst[(kk*8 + c    ) * VP2 + nt*8 + grp]);
                bf2[1] = __float_as_uint(Vst[(kk*8 + c + 4) * VP2 + nt*8 + grp]);
                mma_tf32(o[nt], af2, bf2);
            }
        }
        __syncthreads();
    }

    float inv0 = 1.0f / l0, inv1 = 1.0f / l1;
    size_t grow0 = (size_t)(b * SEQ + qb * 128 + w * 16 + grp);
    size_t grow1 = grow0 + 8;
    #pragma unroll
    for (int nt = 0; nt < 16; nt++) {
        int col = h * HD + nt * 8 + 2 * c;
        float2 v0; v0.x = o[nt][0] * inv0; v0.y = o[nt][1] * inv0;
        float2 v1; v1.x = o[nt][2] * inv1; v1.y = o[nt][3] * inv1;
        *(float2*)&g_attn[grow0 * DIM + col] = v0;
        *(float2*)&g_attn[grow1 * DIM + col] = v1;
    }
}

// =====================================================================
// LayerNorm over last dim (2048). Biased variance. Optional residual add
// and optional second fp16 output (A operand of the next GEMM).
// =====================================================================
template<bool ADDX, bool H16OUT>
__global__ void __launch_bounds__(256) ln_kernel(
    const float* __restrict__ in, const float* __restrict__ add,
    float* __restrict__ out, __half* __restrict__ out_h)
{
    __shared__ float redS[8], redQ[8];
    const int tid = threadIdx.x;
    const size_t base = (size_t)blockIdx.x * DIM;
    float v[8];
    float s = 0.f, q = 0.f;
    #pragma unroll
    for (int k = 0; k < 8; k++) {
        float a = in[base + tid + k*256];
        if (ADDX) a += add[base + tid + k*256];
        v[k] = a; s += a; q += a * a;
    }
    #pragma unroll
    for (int d = 16; d >= 1; d >>= 1) {
        s += __shfl_xor_sync(0xffffffffu, s, d);
        q += __shfl_xor_sync(0xffffffffu, q, d);
    }
    if ((tid & 31) == 0) { redS[tid >> 5] = s; redQ[tid >> 5] = q; }
    __syncthreads();
    float ts = 0.f, tq = 0.f;
    #pragma unroll
    for (int wv = 0; wv < 8; wv++) { ts += redS[wv]; tq += redQ[wv]; }
    float mean = ts * (1.f / DIM);
    float var  = tq * (1.f / DIM) - mean * mean;
    float rstd = rsqrtf(var + 1e-5f);
    #pragma unroll
    for (int k = 0; k < 8; k++) {
        float y = (v[k] - mean) * rstd;
        out[base + tid + k*256] = y;
        if (H16OUT) out_h[base + tid + k*256] = __float2half_rn(y);
    }
}

// =====================================================================
extern "C" void kernel_launch(void* const* d_in, const int* in_sizes, int n_in,
                              void* d_out, int out_size)
{
    const float* x    = (const float*)d_in[0];
    const float* Wq   = (const float*)d_in[1];
    const float* Wk   = (const float*)d_in[2];
    const float* Wv   = (const float*)d_in[3];
    const float* W1   = (const float*)d_in[4];
    const float* b1   = (const float*)d_in[5];
    const float* W2   = (const float*)d_in[6];
    const float* b2   = (const float*)d_in[7];
    const float* sinp = (const float*)d_in[8];
    const float* cosp = (const float*)d_in[9];
    float* out = (float*)d_out;

    float *q, *k, *v, *attn, *ln1;
    __half *xh, *wqh, *wkh, *wvh, *w1h, *w2h, *ln1h, *hbuf;
    cudaGetSymbolAddress((void**)&q,    g_q);
    cudaGetSymbolAddress((void**)&k,    g_k);
    cudaGetSymbolAddress((void**)&v,    g_v);
    cudaGetSymbolAddress((void**)&attn, g_attn);
    cudaGetSymbolAddress((void**)&ln1,  g_ln1);
    cudaGetSymbolAddress((void**)&xh,   g_xh);
    cudaGetSymbolAddress((void**)&wqh,  g_wqh);
    cudaGetSymbolAddress((void**)&wkh,  g_wkh);
    cudaGetSymbolAddress((void**)&wvh,  g_wvh);
    cudaGetSymbolAddress((void**)&w1h,  g_w1h);
    cudaGetSymbolAddress((void**)&w2h,  g_w2h);
    cudaGetSymbolAddress((void**)&ln1h, g_ln1h);
    cudaGetSymbolAddress((void**)&hbuf, g_h);

    cudaFuncSetAttribute(gemm_f16<0,float>,  cudaFuncAttributeMaxDynamicSharedMemorySize, GSMEM_BYTES);
    cudaFuncSetAttribute(gemm_f16<3,float>,  cudaFuncAttributeMaxDynamicSharedMemorySize, GSMEM_BYTES);
    cudaFuncSetAttribute(gemm_f16<1,__half>, cudaFuncAttributeMaxDynamicSharedMemorySize, GSMEM_BYTES);
    cudaFuncSetAttribute(gemm_f16<2,float>,  cudaFuncAttributeMaxDynamicSharedMemorySize, GSMEM_BYTES);
    cudaFuncSetAttribute(attn_mma_kernel, cudaFuncAttributeMaxDynamicSharedMemorySize, ATT_SMEM);

    const dim3 thr(256);
    const dim3 gthr(128);

    // fp16 operand prep
    cvt_f16_kernel<<<2048, thr>>>(x, xh, ((size_t)MROWS*DIM)/4);
    twf16_kernel<<<dim3(DIM/32, DIM/32), thr>>>(Wq, wqh, DIM, DIM);
    twf16_kernel<<<dim3(DIM/32, DIM/32), thr>>>(Wk, wkh, DIM, DIM);
    twf16_kernel<<<dim3(DIM/32, DIM/32), thr>>>(Wv, wvh, DIM, DIM);

    // QKV projections (fp16 mma; V tf32-rounded for attention cp.async)
    gemm_f16<0,float><<<dim3(DIM/128, MROWS/128), gthr, GSMEM_BYTES>>>(xh, wqh, q, nullptr, nullptr, DIM, DIM);
    gemm_f16<0,float><<<dim3(DIM/128, MROWS/128), gthr, GSMEM_BYTES>>>(xh, wkh, k, nullptr, nullptr, DIM, DIM);
    gemm_f16<3,float><<<dim3(DIM/128, MROWS/128), gthr, GSMEM_BYTES>>>(xh, wvh, v, nullptr, nullptr, DIM, DIM);

    // RoPE (batch-indexed sin/cos — reference quirk); outputs tf32-rounded
    rope_kernel<<<MROWS, thr>>>(q, sinp, cosp);
    rope_kernel<<<MROWS, thr>>>(k, sinp, cosp);

    // MLP weight prep
    twf16_kernel<<<dim3(DFF/32, DIM/32), thr>>>(W1, w1h, DIM, DFF);
    twf16_kernel<<<dim3(DIM/32, DFF/32), thr>>>(W2, w2h, DFF, DIM);

    // Tensor-core causal flash attention
    attn_mma_kernel<<<dim3(SEQ/128, NH, BATCH), thr, ATT_SMEM>>>();

    // LN1 with residual (fp32 out for residual; fp16 copy for MLP1 A)
    ln_kernel<true, true><<<MROWS, thr>>>(attn, x, ln1, ln1h);

    // MLP (fp16 mma; gelu output stored fp16)
    gemm_f16<1,__half><<<dim3(DFF/128, MROWS/128), gthr, GSMEM_BYTES>>>(ln1h, w1h, hbuf, b1, nullptr, DFF, DIM);
    gemm_f16<2,float><<<dim3(DIM/128, MROWS/128), gthr, GSMEM_BYTES>>>(hbuf, w2h, q, b2, ln1, DIM, DFF);

    // LN2 -> output
    ln_kernel<false, false><<<MROWS, thr>>>(q, nullptr, out, nullptr);
}